// round 11
// baseline (speedup 1.0000x reference)
#include <cuda_runtime.h>
#include <cuda_bf16.h>
#include <cuda_fp16.h>
#include <cstdint>

#define DIMC   512
#define NHEADS 8
#define HDIM   64
#define BATCH  2
#define SEQ    4096
#define MROWS  (BATCH * SEQ)     // 8192
#define QKVC   (3 * DIMC)        // 1536
#define SEGSZ  (MROWS * DIMC)    // 4194304

typedef unsigned long long u64;

// ------------------------- scratch (device globals) -------------------------
__device__ __nv_bfloat16 g_xh[MROWS * DIMC];
__device__ __nv_bfloat16 g_xl[MROWS * DIMC];
__device__ __nv_bfloat16 g_wqh[QKVC * DIMC];
__device__ __nv_bfloat16 g_wql[QKVC * DIMC];
__device__ __nv_bfloat16 g_wph[DIMC * DIMC];
__device__ __nv_bfloat16 g_wpl[DIMC * DIMC];
__device__ __nv_bfloat16 g_oh[3 * SEGSZ];     // q | k | v  (token-major hi)
__device__ __nv_bfloat16 g_ol[3 * SEGSZ];     // q | k | v  (token-major lo)
__device__ __half        g_vth[SEGSZ];        // V transposed [b][h][d][tok], fp16
__device__ __nv_bfloat16 g_ath[SEGSZ];        // attention out hi
__device__ __nv_bfloat16 g_atl[SEGSZ];        // attention out lo

// ------------------------------ helpers ------------------------------------
__device__ __forceinline__ uint32_t smem_u32(const void* p) {
    uint32_t a;
    asm("{ .reg .u64 t; cvta.to.shared.u64 t, %1; cvt.u32.u64 %0, t; }"
        : "=r"(a) : "l"(p));
    return a;
}
__device__ __forceinline__ float ex2f(float x) {
    float r; asm("ex2.approx.ftz.f32 %0, %1;" : "=f"(r) : "f"(x)); return r;
}
// pack 2 floats -> bf16x2 (first arg in low half)
__device__ __forceinline__ uint32_t cvtbf2(float lo, float hi) {
    uint32_t r;
    asm("cvt.rn.bf16x2.f32 %0, %1, %2;" : "=r"(r) : "f"(hi), "f"(lo));
    return r;
}
// pack 2 floats -> f16x2 (first arg in low half)
__device__ __forceinline__ uint32_t cvthf2(float lo, float hi) {
    uint32_t r;
    asm("cvt.rn.f16x2.f32 %0, %1, %2;" : "=r"(r) : "f"(hi), "f"(lo));
    return r;
}
__device__ __forceinline__ float bfr(float x) {   // round to bf16, back to f32
    return __bfloat162float(__float2bfloat16(x));
}
// warp mma: D(16x8,f32) += A(16x16) * B(16x8)
__device__ __forceinline__ void mma_bf16(float* c, const uint32_t* a,
                                         uint32_t b0, uint32_t b1) {
    asm volatile("mma.sync.aligned.m16n8k16.row.col.f32.bf16.bf16.f32 "
        "{%0,%1,%2,%3}, {%4,%5,%6,%7}, {%8,%9}, {%0,%1,%2,%3};"
        : "+f"(c[0]), "+f"(c[1]), "+f"(c[2]), "+f"(c[3])
        : "r"(a[0]), "r"(a[1]), "r"(a[2]), "r"(a[3]), "r"(b0), "r"(b1));
}
__device__ __forceinline__ void mma_fp16(float* c, const uint32_t* a,
                                         uint32_t b0, uint32_t b1) {
    asm volatile("mma.sync.aligned.m16n8k16.row.col.f32.f16.f16.f32 "
        "{%0,%1,%2,%3}, {%4,%5,%6,%7}, {%8,%9}, {%0,%1,%2,%3};"
        : "+f"(c[0]), "+f"(c[1]), "+f"(c[2]), "+f"(c[3])
        : "r"(a[0]), "r"(a[1]), "r"(a[2]), "r"(a[3]), "r"(b0), "r"(b1));
}
__device__ __forceinline__ void ldsm4(uint32_t addr, uint32_t* d) {
    asm volatile("ldmatrix.sync.aligned.m8n8.x4.shared.b16 {%0,%1,%2,%3}, [%4];"
        : "=r"(d[0]), "=r"(d[1]), "=r"(d[2]), "=r"(d[3]) : "r"(addr));
}
__device__ __forceinline__ void cpasync16(uint32_t s, const void* g) {
    asm volatile("cp.async.cg.shared.global [%0], [%1], 16;" :: "r"(s), "l"(g));
}
#define CP_COMMIT() asm volatile("cp.async.commit_group;" ::: "memory")
#define CP_WAIT0()  asm volatile("cp.async.wait_group 0;" ::: "memory")
#define CP_WAIT1()  asm volatile("cp.async.wait_group 1;" ::: "memory")

// ---------------------------------------------------------------------------
// split_x: fp32 -> bf16 hi/lo
// ---------------------------------------------------------------------------
__global__ __launch_bounds__(256)
void split_x(const float* __restrict__ x,
             __nv_bfloat16* __restrict__ xh, __nv_bfloat16* __restrict__ xl) {
    size_t i = ((size_t)blockIdx.x * 256 + threadIdx.x) * 4;
    float4 v = *(const float4*)&x[i];
    float h0 = bfr(v.x), h1 = bfr(v.y), h2 = bfr(v.z), h3 = bfr(v.w);
    *(uint2*)&xh[i] = make_uint2(cvtbf2(h0, h1), cvtbf2(h2, h3));
    *(uint2*)&xl[i] = make_uint2(cvtbf2(v.x - h0, v.y - h1),
                                 cvtbf2(v.z - h2, v.w - h3));
}

// ---------------------------------------------------------------------------
// split_wT: w[K=512][N] fp32 -> wT[N][512] bf16 hi/lo (transpose + split)
// ---------------------------------------------------------------------------
__global__ __launch_bounds__(256)
void split_wT(const float* __restrict__ w, int N,
              __nv_bfloat16* __restrict__ wth, __nv_bfloat16* __restrict__ wtl) {
    __shared__ float t[32][33];
    const int tid = threadIdx.x;
    const int n0 = blockIdx.x * 32, k0 = blockIdx.y * 32;
    int r = tid >> 3, cq = (tid & 7) * 4;
    float4 v = *(const float4*)&w[(size_t)(k0 + r) * N + n0 + cq];
    t[r][cq + 0] = v.x; t[r][cq + 1] = v.y;
    t[r][cq + 2] = v.z; t[r][cq + 3] = v.w;
    __syncthreads();
    int nr = tid >> 3, kq = (tid & 7) * 4;
    float v0 = t[kq + 0][nr], v1 = t[kq + 1][nr];
    float v2 = t[kq + 2][nr], v3 = t[kq + 3][nr];
    float h0 = bfr(v0), h1 = bfr(v1), h2 = bfr(v2), h3 = bfr(v3);
    size_t o = (size_t)(n0 + nr) * DIMC + k0 + kq;
    *(uint2*)&wth[o] = make_uint2(cvtbf2(h0, h1), cvtbf2(h2, h3));
    *(uint2*)&wtl[o] = make_uint2(cvtbf2(v0 - h0, v1 - h1),
                                  cvtbf2(v2 - h2, v3 - h3));
}

// ---------------------------------------------------------------------------
// gemm_tc: C[M,N] = (Ahi+Alo)[M,512] @ (Bhi+Blo)[512,N], 3 first-order terms.
// BT is [N][512] row-major. CTA 128x64, BK=32, 3-stage cp.async pipeline
// (wait_group 1 keeps one chunk in flight). 8 warps (4x2), warp 32x32.
// ---------------------------------------------------------------------------
#define SA_STR 80                  // bytes/row: 32 bf16 + 16B pad
#define ATILE2 (128 * SA_STR)      // 10240 (A hi or lo)
#define BTILE2 (64 * SA_STR)       // 5120  (B hi or lo)
#define GBUF2  (2 * ATILE2 + 2 * BTILE2)   // 30720
#define GEMM_SMEM (3 * GBUF2)      // 92160

template <bool PROJ>
__global__ __launch_bounds__(256, 2)
void gemm_tc(const __nv_bfloat16* __restrict__ Ahi, const __nv_bfloat16* __restrict__ Alo,
             const __nv_bfloat16* __restrict__ BThi, const __nv_bfloat16* __restrict__ BTlo,
             const float* __restrict__ bias,
             __nv_bfloat16* __restrict__ oh, __nv_bfloat16* __restrict__ ol,
             float* __restrict__ outF) {
    extern __shared__ char smem[];
    const uint32_t sb = smem_u32(smem);
    const int tid = threadIdx.x;
    const int w = tid >> 5, lid = tid & 31;
    const int gid = lid >> 2, tg = lid & 3;
    const int mm = lid >> 3, rr = lid & 7;
    const int wm = w >> 1, wn = w & 1;
    const int bm = blockIdx.y * 128, bn = blockIdx.x * 64;

    auto load_chunk = [&](int k0, int st) {
        uint32_t s0 = sb + st * GBUF2;
#pragma unroll
        for (int l = 0; l < 2; l++) {
            int c = tid + l * 256;
            int row = c >> 2, kc = c & 3;
            uint32_t so = s0 + (uint32_t)(row * SA_STR + kc * 16);
            size_t ga = (size_t)(bm + row) * DIMC + k0 + kc * 8;
            cpasync16(so, Ahi + ga);
            cpasync16(so + ATILE2, Alo + ga);
        }
        {
            int row = tid >> 2, kc = tid & 3;
            uint32_t so = s0 + 2 * ATILE2 + (uint32_t)(row * SA_STR + kc * 16);
            size_t gb = (size_t)(bn + row) * DIMC + k0 + kc * 8;
            cpasync16(so, BThi + gb);
            cpasync16(so + BTILE2, BTlo + gb);
        }
        CP_COMMIT();
    };

    float acc[2][4][4];
#pragma unroll
    for (int i = 0; i < 2; i++)
#pragma unroll
        for (int j = 0; j < 4; j++)
#pragma unroll
            for (int q = 0; q < 4; q++) acc[i][j][q] = 0.f;

    const int NC = DIMC / 32;   // 16
    load_chunk(0, 0);
    load_chunk(32, 1);

    for (int kc = 0; kc < NC; kc++) {
        if (kc + 1 < NC) { CP_WAIT1(); } else { CP_WAIT0(); }
        __syncthreads();
        const int st = kc % 3;
        if (kc + 2 < NC) load_chunk((kc + 2) * 32, (kc + 2) % 3);

        const uint32_t sA = sb + st * GBUF2;
        const uint32_t sB = sA + 2 * ATILE2;
#pragma unroll
        for (int kk = 0; kk < 2; kk++) {
            uint32_t ah[2][4], al[2][4];
#pragma unroll
            for (int i = 0; i < 2; i++) {
                uint32_t a = sA + (uint32_t)((wm * 32 + i * 16 + (mm & 1) * 8 + rr) * SA_STR +
                                             kk * 32 + (mm >> 1) * 16);
                ldsm4(a, ah[i]);
                ldsm4(a + ATILE2, al[i]);
            }
#pragma unroll
            for (int jb = 0; jb < 2; jb++) {
                uint32_t bh[4], bl[4];
                uint32_t a = sB + (uint32_t)((wn * 32 + jb * 16 + (mm >> 1) * 8 + rr) * SA_STR +
                                             kk * 32 + (mm & 1) * 16);
                ldsm4(a, bh);
                ldsm4(a + BTILE2, bl);
#pragma unroll
                for (int i = 0; i < 2; i++) {
                    mma_bf16(acc[i][2 * jb],     ah[i], bh[0], bh[1]);
                    mma_bf16(acc[i][2 * jb + 1], ah[i], bh[2], bh[3]);
                    mma_bf16(acc[i][2 * jb],     ah[i], bl[0], bl[1]);
                    mma_bf16(acc[i][2 * jb + 1], ah[i], bl[2], bl[3]);
                    mma_bf16(acc[i][2 * jb],     al[i], bh[0], bh[1]);
                    mma_bf16(acc[i][2 * jb + 1], al[i], bh[2], bh[3]);
                }
            }
        }
    }

    if (PROJ) {
#pragma unroll
        for (int i = 0; i < 2; i++) {
            int r = bm + wm * 32 + i * 16 + gid;
#pragma unroll
            for (int j = 0; j < 4; j++) {
                int c = bn + wn * 32 + j * 8 + 2 * tg;
                float b0 = bias[c], b1 = bias[c + 1];
                *(float2*)&outF[(size_t)r * DIMC + c] =
                    make_float2(acc[i][j][0] + b0, acc[i][j][1] + b1);
                *(float2*)&outF[(size_t)(r + 8) * DIMC + c] =
                    make_float2(acc[i][j][2] + b0, acc[i][j][3] + b1);
            }
        }
    } else {
        const int seg = bn >> 9;
        const size_t so = (size_t)seg * SEGSZ;
        const int cb = (bn & 511) + wn * 32;
#pragma unroll
        for (int i = 0; i < 2; i++) {
            int r = bm + wm * 32 + i * 16 + gid;
#pragma unroll
            for (int j = 0; j < 4; j++) {
                int c = cb + j * 8 + 2 * tg;
                float v0 = acc[i][j][0], v1 = acc[i][j][1];
                float v2 = acc[i][j][2], v3 = acc[i][j][3];
                float h0 = bfr(v0), h1 = bfr(v1), h2 = bfr(v2), h3 = bfr(v3);
                *(uint32_t*)&oh[so + (size_t)r * DIMC + c] = cvtbf2(h0, h1);
                *(uint32_t*)&ol[so + (size_t)r * DIMC + c] = cvtbf2(v0 - h0, v1 - h1);
                *(uint32_t*)&oh[so + (size_t)(r + 8) * DIMC + c] = cvtbf2(h2, h3);
                *(uint32_t*)&ol[so + (size_t)(r + 8) * DIMC + c] = cvtbf2(v2 - h2, v3 - h3);
            }
        }
    }
}

// ---------------------------------------------------------------------------
// transpose_v: bf16 hi/lo [b*tok][512] -> fp16 [b][h][d][SEQ] (v = hi + lo)
// ---------------------------------------------------------------------------
__global__ __launch_bounds__(256)
void transpose_v(const __nv_bfloat16* __restrict__ vh, const __nv_bfloat16* __restrict__ vl,
                 __half* __restrict__ vt) {
    __shared__ float t[64][129];
    const int tid = threadIdx.x;
    const int tt = blockIdx.x, h = blockIdx.y, b = blockIdx.z;
    const int tok0 = tt * 128;
    const size_t ibase = ((size_t)(b * SEQ + tok0)) * DIMC + h * 64;
    const size_t obase = ((size_t)((b * NHEADS + h) * HDIM)) * SEQ + tok0;

#pragma unroll
    for (int l = 0; l < 16; l++) {
        int idx = tid + l * 256;                 // 4096 = 128 tok x 32 du
        int tok = idx >> 5, du = idx & 31;
        uint32_t uh = *(const uint32_t*)(vh + ibase + (size_t)tok * DIMC + 2 * du);
        uint32_t ul = *(const uint32_t*)(vl + ibase + (size_t)tok * DIMC + 2 * du);
        float f0 = __bfloat162float(((__nv_bfloat16*)&uh)[0]) +
                   __bfloat162float(((__nv_bfloat16*)&ul)[0]);
        float f1 = __bfloat162float(((__nv_bfloat16*)&uh)[1]) +
                   __bfloat162float(((__nv_bfloat16*)&ul)[1]);
        t[2 * du + 0][tok] = f0;
        t[2 * du + 1][tok] = f1;
    }
    __syncthreads();
#pragma unroll
    for (int l = 0; l < 4; l++) {
        int idx = tid + l * 256;                 // 1024 = 64 d x 16 chunks
        int d = idx >> 4, tq = (idx & 15) * 8;
        uint4 o;
        o.x = cvthf2(t[d][tq + 0], t[d][tq + 1]);
        o.y = cvthf2(t[d][tq + 2], t[d][tq + 3]);
        o.z = cvthf2(t[d][tq + 4], t[d][tq + 5]);
        o.w = cvthf2(t[d][tq + 6], t[d][tq + 7]);
        *(uint4*)(vt + obase + (size_t)d * SEQ + tq) = o;
    }
}

// ---------------------------------------------------------------------------
// mma.sync flash attention. S = bf16 3-term; PV = single fp16 (P fp16, V fp16).
// ---------------------------------------------------------------------------
#define KSTRB  144
#define VSTRB  272
#define KBYTES (128 * KSTRB)           // 18432
#define VBYTES (64 * VSTRB)            // 17408
#define BUFSZ  (2 * KBYTES + VBYTES)   // 54272
#define FL_SMEM (2 * BUFSZ)            // 108544

__global__ __launch_bounds__(256, 1)
void flash_mma(const __nv_bfloat16* __restrict__ qhi, const __nv_bfloat16* __restrict__ qlo,
               const __nv_bfloat16* __restrict__ khi, const __nv_bfloat16* __restrict__ klo,
               const __half* __restrict__ vt,
               __nv_bfloat16* __restrict__ ath, __nv_bfloat16* __restrict__ atl) {
    extern __shared__ char smem[];
    const uint32_t sb = smem_u32(smem);
    const int tid = threadIdx.x;
    const int w = tid >> 5, lid = tid & 31;
    const int gid = lid >> 2, tg = lid & 3;
    const int mm = lid >> 3, rr = lid & 7;
    const int m0 = blockIdx.x * 128, h = blockIdx.y, b = blockIdx.z;

    auto load_tile = [&](int n0, int bf) {
        uint32_t sk = sb + bf * BUFSZ;
        size_t kb = ((size_t)(b * SEQ + n0)) * DIMC + h * 64;
#pragma unroll
        for (int l = 0; l < 4; l++) {
            int c = tid + l * 256;
            int row = c >> 3, c8 = c & 7;
            uint32_t so = sk + (uint32_t)(row * KSTRB + c8 * 16);
            const size_t go = kb + (size_t)row * DIMC + c8 * 8;
            cpasync16(so, khi + go);
            cpasync16(so + KBYTES, klo + go);
        }
        uint32_t sv = sk + 2 * KBYTES;
        size_t vb = ((size_t)((b * NHEADS + h) * HDIM)) * SEQ + n0;
#pragma unroll
        for (int l = 0; l < 4; l++) {
            int c = tid + l * 256;
            int d = c >> 4, kc = c & 15;
            uint32_t so = sv + (uint32_t)(d * VSTRB + kc * 16);
            cpasync16(so, vt + vb + (size_t)d * SEQ + kc * 8);
        }
        CP_COMMIT();
    };

    load_tile(0, 0);

    uint32_t qh[16], ql[16];
    {
        const size_t qb = ((size_t)(b * SEQ + m0 + w * 16 + gid)) * DIMC + h * 64;
#pragma unroll
        for (int ks = 0; ks < 4; ks++) {
            qh[ks * 4 + 0] = *(const uint32_t*)(qhi + qb + ks * 16 + 2 * tg);
            qh[ks * 4 + 1] = *(const uint32_t*)(qhi + qb + 8 * DIMC + ks * 16 + 2 * tg);
            qh[ks * 4 + 2] = *(const uint32_t*)(qhi + qb + ks * 16 + 8 + 2 * tg);
            qh[ks * 4 + 3] = *(const uint32_t*)(qhi + qb + 8 * DIMC + ks * 16 + 8 + 2 * tg);
            ql[ks * 4 + 0] = *(const uint32_t*)(qlo + qb + ks * 16 + 2 * tg);
            ql[ks * 4 + 1] = *(const uint32_t*)(qlo + qb + 8 * DIMC + ks * 16 + 2 * tg);
            ql[ks * 4 + 2] = *(const uint32_t*)(qlo + qb + ks * 16 + 8 + 2 * tg);
            ql[ks * 4 + 3] = *(const uint32_t*)(qlo + qb + 8 * DIMC + ks * 16 + 8 + 2 * tg);
        }
    }

    float oacc[32];
#pragma unroll
    for (int i = 0; i < 32; i++) oacc[i] = 0.f;
    float lsum_lo = 0.f, lsum_hi = 0.f;
    const float cexp = 0.125f * 1.4426950408889634f;

    const int NT = SEQ / 128;
    for (int it = 0; it < NT; it++) {
        const int bf = it & 1;
        CP_WAIT0();
        __syncthreads();
        if (it + 1 < NT) load_tile((it + 1) * 128, (it + 1) & 1);

        const uint32_t sbK = sb + bf * BUFSZ;
        const uint32_t sbV = sbK + 2 * KBYTES;

        float s[64];
#pragma unroll
        for (int i = 0; i < 64; i++) s[i] = 0.f;
        uint32_t pr[32];

        // softmax for one 8-score block: s -> fp16 P frags + row-sum
        auto softmax_block = [&](int ks) {
            float p0 = ex2f(s[ks * 8 + 0] * cexp);
            float p1 = ex2f(s[ks * 8 + 1] * cexp);
            float p2 = ex2f(s[ks * 8 + 2] * cexp);
            float p3 = ex2f(s[ks * 8 + 3] * cexp);
            float p4 = ex2f(s[ks * 8 + 4] * cexp);
            float p5 = ex2f(s[ks * 8 + 5] * cexp);
            float p6 = ex2f(s[ks * 8 + 6] * cexp);
            float p7 = ex2f(s[ks * 8 + 7] * cexp);
            lsum_lo += (p0 + p1) + (p4 + p5);
            lsum_hi += (p2 + p3) + (p6 + p7);
            pr[ks * 4 + 0] = cvthf2(p0, p1);
            pr[ks * 4 + 1] = cvthf2(p2, p3);
            pr[ks * 4 + 2] = cvthf2(p4, p5);
            pr[ks * 4 + 3] = cvthf2(p6, p7);
        };

        // S = (Qhi+Qlo)(Khi+Klo)^T, 3 first-order terms; softmax interleaved
#pragma unroll
        for (int nb2 = 0; nb2 < 8; nb2++) {
#pragma unroll
            for (int ks = 0; ks < 4; ks++) {
                uint32_t a = sbK + (uint32_t)((nb2 * 16 + (mm >> 1) * 8 + rr) * KSTRB +
                                              ks * 32 + (mm & 1) * 16);
                uint32_t kh[4], kl[4];
                ldsm4(a, kh);
                ldsm4(a + KBYTES, kl);
                mma_bf16(&s[nb2 * 8 + 0], &qh[ks * 4], kh[0], kh[1]);
                mma_bf16(&s[nb2 * 8 + 4], &qh[ks * 4], kh[2], kh[3]);
                mma_bf16(&s[nb2 * 8 + 0], &qh[ks * 4], kl[0], kl[1]);
                mma_bf16(&s[nb2 * 8 + 4], &qh[ks * 4], kl[2], kl[3]);
                mma_bf16(&s[nb2 * 8 + 0], &ql[ks * 4], kh[0], kh[1]);
                mma_bf16(&s[nb2 * 8 + 4], &ql[ks * 4], kh[2], kh[3]);
            }
            if (nb2 > 0) softmax_block(nb2 - 1);
        }
        softmax_block(7);

        // O += P @ V, single fp16 term
#pragma unroll
        for (int nb2 = 0; nb2 < 4; nb2++) {
#pragma unroll
            for (int ks = 0; ks < 8; ks++) {
                uint32_t a = sbV + (uint32_t)((nb2 * 16 + (mm >> 1) * 8 + rr) * VSTRB +
                                              ks * 32 + (mm & 1) * 16);
                uint32_t vh[4];
                ldsm4(a, vh);
                mma_fp16(&oacc[nb2 * 8 + 0], &pr[ks * 4], vh[0], vh[1]);
                mma_fp16(&oacc[nb2 * 8 + 4], &pr[ks * 4], vh[2], vh[3]);
            }
        }
    }

    lsum_lo += __shfl_xor_sync(0xffffffffu, lsum_lo, 1);
    lsum_lo += __shfl_xor_sync(0xffffffffu, lsum_lo, 2);
    lsum_hi += __shfl_xor_sync(0xffffffffu, lsum_hi, 1);
    lsum_hi += __shfl_xor_sync(0xffffffffu, lsum_hi, 2);
    float ilo = 1.0f / lsum_lo;
    float ihi = 1.0f / lsum_hi;

    const int row_lo = m0 + w * 16 + gid;
    const size_t ob = ((size_t)(b * SEQ + row_lo)) * DIMC + h * 64 + 2 * tg;
#pragma unroll
    for (int nb = 0; nb < 8; nb++) {
        float o0 = oacc[nb * 4 + 0] * ilo, o1 = oacc[nb * 4 + 1] * ilo;
        float h0 = bfr(o0), h1 = bfr(o1);
        *(uint32_t*)&ath[ob + nb * 8] = cvtbf2(h0, h1);
        *(uint32_t*)&atl[ob + nb * 8] = cvtbf2(o0 - h0, o1 - h1);
        float o2 = oacc[nb * 4 + 2] * ihi, o3 = oacc[nb * 4 + 3] * ihi;
        float h2 = bfr(o2), h3 = bfr(o3);
        *(uint32_t*)&ath[ob + 8 * DIMC + nb * 8] = cvtbf2(h2, h3);
        *(uint32_t*)&atl[ob + 8 * DIMC + nb * 8] = cvtbf2(o2 - h2, o3 - h3);
    }
}

// ---------------------------------------------------------------------------
extern "C" void kernel_launch(void* const* d_in, const int* in_sizes, int n_in,
                              void* d_out, int out_size) {
    const float* x      = (const float*)d_in[0];
    const float* w_qkv  = (const float*)d_in[1];
    const float* w_proj = (const float*)d_in[2];
    const float* b_proj = (const float*)d_in[3];
    float* out = (float*)d_out;

    void *xh, *xl, *wqh, *wql, *wph, *wpl, *oh, *ol, *vth, *ath, *atl;
    cudaGetSymbolAddress(&xh, g_xh);   cudaGetSymbolAddress(&xl, g_xl);
    cudaGetSymbolAddress(&wqh, g_wqh); cudaGetSymbolAddress(&wql, g_wql);
    cudaGetSymbolAddress(&wph, g_wph); cudaGetSymbolAddress(&wpl, g_wpl);
    cudaGetSymbolAddress(&oh, g_oh);   cudaGetSymbolAddress(&ol, g_ol);
    cudaGetSymbolAddress(&vth, g_vth);
    cudaGetSymbolAddress(&ath, g_ath); cudaGetSymbolAddress(&atl, g_atl);

    typedef __nv_bfloat16 bf;

    cudaFuncSetAttribute(flash_mma,
                         cudaFuncAttributeMaxDynamicSharedMemorySize, FL_SMEM);
    cudaFuncSetAttribute(gemm_tc<false>,
                         cudaFuncAttributeMaxDynamicSharedMemorySize, GEMM_SMEM);
    cudaFuncSetAttribute(gemm_tc<true>,
                         cudaFuncAttributeMaxDynamicSharedMemorySize, GEMM_SMEM);

    // 1) splits
    split_x<<<MROWS * DIMC / 4 / 256, 256>>>(x, (bf*)xh, (bf*)xl);
    split_wT<<<dim3(QKVC / 32, DIMC / 32), 256>>>(w_qkv, QKVC, (bf*)wqh, (bf*)wql);
    split_wT<<<dim3(DIMC / 32, DIMC / 32), 256>>>(w_proj, DIMC, (bf*)wph, (bf*)wpl);

    // 2) QKV projection (tensor) -> segmented q|k|v hi/lo
    gemm_tc<false><<<dim3(QKVC / 64, MROWS / 128), 256, GEMM_SMEM>>>(
        (const bf*)xh, (const bf*)xl, (const bf*)wqh, (const bf*)wql,
        nullptr, (bf*)oh, (bf*)ol, nullptr);

    // 3) V transpose -> fp16
    transpose_v<<<dim3(SEQ / 128, NHEADS, BATCH), 256>>>(
        (const bf*)oh + 2 * (size_t)SEGSZ, (const bf*)ol + 2 * (size_t)SEGSZ,
        (__half*)vth);

    // 4) flash attention -> att bf16 hi/lo
    flash_mma<<<dim3(SEQ / 128, NHEADS, BATCH), 256, FL_SMEM>>>(
        (const bf*)oh, (const bf*)ol,
        (const bf*)oh + (size_t)SEGSZ, (const bf*)ol + (size_t)SEGSZ,
        (const __half*)vth, (bf*)ath, (bf*)atl);

    // 5) output projection (tensor) + bias -> fp32 out
    gemm_tc<true><<<dim3(DIMC / 64, MROWS / 128), 256, GEMM_SMEM>>>(
        (const bf*)ath, (const bf*)atl, (const bf*)wph, (const bf*)wpl,
        b_proj, nullptr, nullptr, out);
}

// round 12
// speedup vs baseline: 1.5537x; 1.5537x over previous
#include <cuda_runtime.h>
#include <cuda_bf16.h>
#include <cuda_fp16.h>
#include <cstdint>

#define DIMC   512
#define NHEADS 8
#define HDIM   64
#define BATCH  2
#define SEQ    4096
#define MROWS  (BATCH * SEQ)     // 8192
#define QKVC   (3 * DIMC)        // 1536
#define SEGSZ  (MROWS * DIMC)    // 4194304

typedef unsigned long long u64;

// ------------------------- scratch (device globals) -------------------------
__device__ __nv_bfloat16 g_xh[MROWS * DIMC];
__device__ __nv_bfloat16 g_xl[MROWS * DIMC];
__device__ __nv_bfloat16 g_wqh[QKVC * DIMC];
__device__ __nv_bfloat16 g_wql[QKVC * DIMC];
__device__ __nv_bfloat16 g_wph[DIMC * DIMC];
__device__ __nv_bfloat16 g_wpl[DIMC * DIMC];
__device__ __nv_bfloat16 g_oh[3 * SEGSZ];     // q | k | v  (token-major hi)
__device__ __nv_bfloat16 g_ol[3 * SEGSZ];     // q | k | v  (token-major lo)
__device__ __half        g_vth[SEGSZ];        // V transposed [b][h][d][tok], fp16
__device__ __nv_bfloat16 g_ath[SEGSZ];        // attention out hi
__device__ __nv_bfloat16 g_atl[SEGSZ];        // attention out lo

// ------------------------------ helpers ------------------------------------
__device__ __forceinline__ uint32_t smem_u32(const void* p) {
    uint32_t a;
    asm("{ .reg .u64 t; cvta.to.shared.u64 t, %1; cvt.u32.u64 %0, t; }"
        : "=r"(a) : "l"(p));
    return a;
}
__device__ __forceinline__ float ex2f(float x) {
    float r; asm("ex2.approx.ftz.f32 %0, %1;" : "=f"(r) : "f"(x)); return r;
}
// pack 2 floats -> bf16x2 (first arg in low half)
__device__ __forceinline__ uint32_t cvtbf2(float lo, float hi) {
    uint32_t r;
    asm("cvt.rn.bf16x2.f32 %0, %1, %2;" : "=r"(r) : "f"(hi), "f"(lo));
    return r;
}
// pack 2 floats -> f16x2 (first arg in low half)
__device__ __forceinline__ uint32_t cvthf2(float lo, float hi) {
    uint32_t r;
    asm("cvt.rn.f16x2.f32 %0, %1, %2;" : "=r"(r) : "f"(hi), "f"(lo));
    return r;
}
__device__ __forceinline__ float bfr(float x) {   // round to bf16, back to f32
    return __bfloat162float(__float2bfloat16(x));
}
// warp mma: D(16x8,f32) += A(16x16) * B(16x8)
__device__ __forceinline__ void mma_bf16(float* c, const uint32_t* a,
                                         uint32_t b0, uint32_t b1) {
    asm volatile("mma.sync.aligned.m16n8k16.row.col.f32.bf16.bf16.f32 "
        "{%0,%1,%2,%3}, {%4,%5,%6,%7}, {%8,%9}, {%0,%1,%2,%3};"
        : "+f"(c[0]), "+f"(c[1]), "+f"(c[2]), "+f"(c[3])
        : "r"(a[0]), "r"(a[1]), "r"(a[2]), "r"(a[3]), "r"(b0), "r"(b1));
}
__device__ __forceinline__ void mma_fp16(float* c, const uint32_t* a,
                                         uint32_t b0, uint32_t b1) {
    asm volatile("mma.sync.aligned.m16n8k16.row.col.f32.f16.f16.f32 "
        "{%0,%1,%2,%3}, {%4,%5,%6,%7}, {%8,%9}, {%0,%1,%2,%3};"
        : "+f"(c[0]), "+f"(c[1]), "+f"(c[2]), "+f"(c[3])
        : "r"(a[0]), "r"(a[1]), "r"(a[2]), "r"(a[3]), "r"(b0), "r"(b1));
}
__device__ __forceinline__ void ldsm4(uint32_t addr, uint32_t* d) {
    asm volatile("ldmatrix.sync.aligned.m8n8.x4.shared.b16 {%0,%1,%2,%3}, [%4];"
        : "=r"(d[0]), "=r"(d[1]), "=r"(d[2]), "=r"(d[3]) : "r"(addr));
}
__device__ __forceinline__ void cpasync16(uint32_t s, const void* g) {
    asm volatile("cp.async.cg.shared.global [%0], [%1], 16;" :: "r"(s), "l"(g));
}
#define CP_COMMIT() asm volatile("cp.async.commit_group;" ::: "memory")
#define CP_WAIT0()  asm volatile("cp.async.wait_group 0;" ::: "memory")

// ---------------------------------------------------------------------------
// split_x: fp32 -> bf16 hi/lo
// ---------------------------------------------------------------------------
__global__ __launch_bounds__(256)
void split_x(const float* __restrict__ x,
             __nv_bfloat16* __restrict__ xh, __nv_bfloat16* __restrict__ xl) {
    size_t i = ((size_t)blockIdx.x * 256 + threadIdx.x) * 4;
    float4 v = *(const float4*)&x[i];
    float h0 = bfr(v.x), h1 = bfr(v.y), h2 = bfr(v.z), h3 = bfr(v.w);
    *(uint2*)&xh[i] = make_uint2(cvtbf2(h0, h1), cvtbf2(h2, h3));
    *(uint2*)&xl[i] = make_uint2(cvtbf2(v.x - h0, v.y - h1),
                                 cvtbf2(v.z - h2, v.w - h3));
}

// ---------------------------------------------------------------------------
// split_wT: w[K=512][N] fp32 -> wT[N][512] bf16 hi/lo (transpose + split)
// ---------------------------------------------------------------------------
__global__ __launch_bounds__(256)
void split_wT(const float* __restrict__ w, int N,
              __nv_bfloat16* __restrict__ wth, __nv_bfloat16* __restrict__ wtl) {
    __shared__ float t[32][33];
    const int tid = threadIdx.x;
    const int n0 = blockIdx.x * 32, k0 = blockIdx.y * 32;
    int r = tid >> 3, cq = (tid & 7) * 4;
    float4 v = *(const float4*)&w[(size_t)(k0 + r) * N + n0 + cq];
    t[r][cq + 0] = v.x; t[r][cq + 1] = v.y;
    t[r][cq + 2] = v.z; t[r][cq + 3] = v.w;
    __syncthreads();
    int nr = tid >> 3, kq = (tid & 7) * 4;
    float v0 = t[kq + 0][nr], v1 = t[kq + 1][nr];
    float v2 = t[kq + 2][nr], v3 = t[kq + 3][nr];
    float h0 = bfr(v0), h1 = bfr(v1), h2 = bfr(v2), h3 = bfr(v3);
    size_t o = (size_t)(n0 + nr) * DIMC + k0 + kq;
    *(uint2*)&wth[o] = make_uint2(cvtbf2(h0, h1), cvtbf2(h2, h3));
    *(uint2*)&wtl[o] = make_uint2(cvtbf2(v0 - h0, v1 - h1),
                                  cvtbf2(v2 - h2, v3 - h3));
}

// ---------------------------------------------------------------------------
// gemm_tc: EXACT R10 version (2-stage double buffer; known 128us on QKV).
// C[M,N] = (Ahi+Alo)[M,512] @ (Bhi+Blo)[512,N], 3 first-order terms.
// CTA 128x64, BK=32, 8 warps (4x2), warp 32x32, 2 CTAs/SM.
// ---------------------------------------------------------------------------
#define SA_STR 80                  // bytes/row: 32 bf16 + 16B pad
#define ATILE2 (128 * SA_STR)      // 10240 (A hi or lo)
#define BTILE2 (64 * SA_STR)       // 5120  (B hi or lo)
#define GBUF2  (2 * ATILE2 + 2 * BTILE2)   // 30720
#define GEMM_SMEM (2 * GBUF2)      // 61440

template <bool PROJ>
__global__ __launch_bounds__(256, 2)
void gemm_tc(const __nv_bfloat16* __restrict__ Ahi, const __nv_bfloat16* __restrict__ Alo,
             const __nv_bfloat16* __restrict__ BThi, const __nv_bfloat16* __restrict__ BTlo,
             const float* __restrict__ bias,
             __nv_bfloat16* __restrict__ oh, __nv_bfloat16* __restrict__ ol,
             float* __restrict__ outF) {
    extern __shared__ char smem[];
    const uint32_t sb = smem_u32(smem);
    const int tid = threadIdx.x;
    const int w = tid >> 5, lid = tid & 31;
    const int gid = lid >> 2, tg = lid & 3;
    const int mm = lid >> 3, rr = lid & 7;
    const int wm = w >> 1, wn = w & 1;
    const int bm = blockIdx.y * 128, bn = blockIdx.x * 64;

    auto load_chunk = [&](int k0, int bf) {
        uint32_t s0 = sb + bf * GBUF2;
#pragma unroll
        for (int l = 0; l < 2; l++) {
            int c = tid + l * 256;
            int row = c >> 2, kc = c & 3;
            uint32_t so = s0 + (uint32_t)(row * SA_STR + kc * 16);
            size_t ga = (size_t)(bm + row) * DIMC + k0 + kc * 8;
            cpasync16(so, Ahi + ga);
            cpasync16(so + ATILE2, Alo + ga);
        }
        {
            int row = tid >> 2, kc = tid & 3;
            uint32_t so = s0 + 2 * ATILE2 + (uint32_t)(row * SA_STR + kc * 16);
            size_t gb = (size_t)(bn + row) * DIMC + k0 + kc * 8;
            cpasync16(so, BThi + gb);
            cpasync16(so + BTILE2, BTlo + gb);
        }
        CP_COMMIT();
    };

    float acc[2][4][4];
#pragma unroll
    for (int i = 0; i < 2; i++)
#pragma unroll
        for (int j = 0; j < 4; j++)
#pragma unroll
            for (int q = 0; q < 4; q++) acc[i][j][q] = 0.f;

    load_chunk(0, 0);

    const int NC = DIMC / 32;   // 16
    for (int kc = 0; kc < NC; kc++) {
        const int bf = kc & 1;
        CP_WAIT0();
        __syncthreads();
        if (kc + 1 < NC) load_chunk((kc + 1) * 32, (kc + 1) & 1);

        const uint32_t sA = sb + bf * GBUF2;
        const uint32_t sB = sA + 2 * ATILE2;
#pragma unroll
        for (int kk = 0; kk < 2; kk++) {
            uint32_t ah[2][4], al[2][4];
#pragma unroll
            for (int i = 0; i < 2; i++) {
                uint32_t a = sA + (uint32_t)((wm * 32 + i * 16 + (mm & 1) * 8 + rr) * SA_STR +
                                             kk * 32 + (mm >> 1) * 16);
                ldsm4(a, ah[i]);
                ldsm4(a + ATILE2, al[i]);
            }
#pragma unroll
            for (int jb = 0; jb < 2; jb++) {
                uint32_t bh[4], bl[4];
                uint32_t a = sB + (uint32_t)((wn * 32 + jb * 16 + (mm >> 1) * 8 + rr) * SA_STR +
                                             kk * 32 + (mm & 1) * 16);
                ldsm4(a, bh);
                ldsm4(a + BTILE2, bl);
#pragma unroll
                for (int i = 0; i < 2; i++) {
                    mma_bf16(acc[i][2 * jb],     ah[i], bh[0], bh[1]);
                    mma_bf16(acc[i][2 * jb + 1], ah[i], bh[2], bh[3]);
                    mma_bf16(acc[i][2 * jb],     ah[i], bl[0], bl[1]);
                    mma_bf16(acc[i][2 * jb + 1], ah[i], bl[2], bl[3]);
                    mma_bf16(acc[i][2 * jb],     al[i], bh[0], bh[1]);
                    mma_bf16(acc[i][2 * jb + 1], al[i], bh[2], bh[3]);
                }
            }
        }
    }

    if (PROJ) {
#pragma unroll
        for (int i = 0; i < 2; i++) {
            int r = bm + wm * 32 + i * 16 + gid;
#pragma unroll
            for (int j = 0; j < 4; j++) {
                int c = bn + wn * 32 + j * 8 + 2 * tg;
                float b0 = bias[c], b1 = bias[c + 1];
                *(float2*)&outF[(size_t)r * DIMC + c] =
                    make_float2(acc[i][j][0] + b0, acc[i][j][1] + b1);
                *(float2*)&outF[(size_t)(r + 8) * DIMC + c] =
                    make_float2(acc[i][j][2] + b0, acc[i][j][3] + b1);
            }
        }
    } else {
        const int seg = bn >> 9;
        const size_t so = (size_t)seg * SEGSZ;
        const int cb = (bn & 511) + wn * 32;
#pragma unroll
        for (int i = 0; i < 2; i++) {
            int r = bm + wm * 32 + i * 16 + gid;
#pragma unroll
            for (int j = 0; j < 4; j++) {
                int c = cb + j * 8 + 2 * tg;
                float v0 = acc[i][j][0], v1 = acc[i][j][1];
                float v2 = acc[i][j][2], v3 = acc[i][j][3];
                float h0 = bfr(v0), h1 = bfr(v1), h2 = bfr(v2), h3 = bfr(v3);
                *(uint32_t*)&oh[so + (size_t)r * DIMC + c] = cvtbf2(h0, h1);
                *(uint32_t*)&ol[so + (size_t)r * DIMC + c] = cvtbf2(v0 - h0, v1 - h1);
                *(uint32_t*)&oh[so + (size_t)(r + 8) * DIMC + c] = cvtbf2(h2, h3);
                *(uint32_t*)&ol[so + (size_t)(r + 8) * DIMC + c] = cvtbf2(v2 - h2, v3 - h3);
            }
        }
    }
}

// ---------------------------------------------------------------------------
// transpose_v: bf16 hi/lo [b*tok][512] -> fp16 [b][h][d][SEQ] (v = hi + lo)
// ---------------------------------------------------------------------------
__global__ __launch_bounds__(256)
void transpose_v(const __nv_bfloat16* __restrict__ vh, const __nv_bfloat16* __restrict__ vl,
                 __half* __restrict__ vt) {
    __shared__ float t[64][129];
    const int tid = threadIdx.x;
    const int tt = blockIdx.x, h = blockIdx.y, b = blockIdx.z;
    const int tok0 = tt * 128;
    const size_t ibase = ((size_t)(b * SEQ + tok0)) * DIMC + h * 64;
    const size_t obase = ((size_t)((b * NHEADS + h) * HDIM)) * SEQ + tok0;

#pragma unroll
    for (int l = 0; l < 16; l++) {
        int idx = tid + l * 256;                 // 4096 = 128 tok x 32 du
        int tok = idx >> 5, du = idx & 31;
        uint32_t uh = *(const uint32_t*)(vh + ibase + (size_t)tok * DIMC + 2 * du);
        uint32_t ul = *(const uint32_t*)(vl + ibase + (size_t)tok * DIMC + 2 * du);
        float f0 = __bfloat162float(((__nv_bfloat16*)&uh)[0]) +
                   __bfloat162float(((__nv_bfloat16*)&ul)[0]);
        float f1 = __bfloat162float(((__nv_bfloat16*)&uh)[1]) +
                   __bfloat162float(((__nv_bfloat16*)&ul)[1]);
        t[2 * du + 0][tok] = f0;
        t[2 * du + 1][tok] = f1;
    }
    __syncthreads();
#pragma unroll
    for (int l = 0; l < 4; l++) {
        int idx = tid + l * 256;                 // 1024 = 64 d x 16 chunks
        int d = idx >> 4, tq = (idx & 15) * 8;
        uint4 o;
        o.x = cvthf2(t[d][tq + 0], t[d][tq + 1]);
        o.y = cvthf2(t[d][tq + 2], t[d][tq + 3]);
        o.z = cvthf2(t[d][tq + 4], t[d][tq + 5]);
        o.w = cvthf2(t[d][tq + 6], t[d][tq + 7]);
        *(uint4*)(vt + obase + (size_t)d * SEQ + tq) = o;
    }
}

// ---------------------------------------------------------------------------
// mma.sync flash attention. S = bf16 3-term; PV = single fp16 (P fp16, V fp16).
// ---------------------------------------------------------------------------
#define KSTRB  144
#define VSTRB  272
#define KBYTES (128 * KSTRB)           // 18432
#define VBYTES (64 * VSTRB)            // 17408
#define BUFSZ  (2 * KBYTES + VBYTES)   // 54272
#define FL_SMEM (2 * BUFSZ)            // 108544

__global__ __launch_bounds__(256, 1)
void flash_mma(const __nv_bfloat16* __restrict__ qhi, const __nv_bfloat16* __restrict__ qlo,
               const __nv_bfloat16* __restrict__ khi, const __nv_bfloat16* __restrict__ klo,
               const __half* __restrict__ vt,
               __nv_bfloat16* __restrict__ ath, __nv_bfloat16* __restrict__ atl) {
    extern __shared__ char smem[];
    const uint32_t sb = smem_u32(smem);
    const int tid = threadIdx.x;
    const int w = tid >> 5, lid = tid & 31;
    const int gid = lid >> 2, tg = lid & 3;
    const int mm = lid >> 3, rr = lid & 7;
    const int m0 = blockIdx.x * 128, h = blockIdx.y, b = blockIdx.z;

    auto load_tile = [&](int n0, int bf) {
        uint32_t sk = sb + bf * BUFSZ;
        size_t kb = ((size_t)(b * SEQ + n0)) * DIMC + h * 64;
#pragma unroll
        for (int l = 0; l < 4; l++) {
            int c = tid + l * 256;
            int row = c >> 3, c8 = c & 7;
            uint32_t so = sk + (uint32_t)(row * KSTRB + c8 * 16);
            const size_t go = kb + (size_t)row * DIMC + c8 * 8;
            cpasync16(so, khi + go);
            cpasync16(so + KBYTES, klo + go);
        }
        uint32_t sv = sk + 2 * KBYTES;
        size_t vb = ((size_t)((b * NHEADS + h) * HDIM)) * SEQ + n0;
#pragma unroll
        for (int l = 0; l < 4; l++) {
            int c = tid + l * 256;
            int d = c >> 4, kc = c & 15;
            uint32_t so = sv + (uint32_t)(d * VSTRB + kc * 16);
            cpasync16(so, vt + vb + (size_t)d * SEQ + kc * 8);
        }
        CP_COMMIT();
    };

    load_tile(0, 0);

    uint32_t qh[16], ql[16];
    {
        const size_t qb = ((size_t)(b * SEQ + m0 + w * 16 + gid)) * DIMC + h * 64;
#pragma unroll
        for (int ks = 0; ks < 4; ks++) {
            qh[ks * 4 + 0] = *(const uint32_t*)(qhi + qb + ks * 16 + 2 * tg);
            qh[ks * 4 + 1] = *(const uint32_t*)(qhi + qb + 8 * DIMC + ks * 16 + 2 * tg);
            qh[ks * 4 + 2] = *(const uint32_t*)(qhi + qb + ks * 16 + 8 + 2 * tg);
            qh[ks * 4 + 3] = *(const uint32_t*)(qhi + qb + 8 * DIMC + ks * 16 + 8 + 2 * tg);
            ql[ks * 4 + 0] = *(const uint32_t*)(qlo + qb + ks * 16 + 2 * tg);
            ql[ks * 4 + 1] = *(const uint32_t*)(qlo + qb + 8 * DIMC + ks * 16 + 2 * tg);
            ql[ks * 4 + 2] = *(const uint32_t*)(qlo + qb + ks * 16 + 8 + 2 * tg);
            ql[ks * 4 + 3] = *(const uint32_t*)(qlo + qb + 8 * DIMC + ks * 16 + 8 + 2 * tg);
        }
    }

    float oacc[32];
#pragma unroll
    for (int i = 0; i < 32; i++) oacc[i] = 0.f;
    float lsum_lo = 0.f, lsum_hi = 0.f;
    const float cexp = 0.125f * 1.4426950408889634f;

    const int NT = SEQ / 128;
    for (int it = 0; it < NT; it++) {
        const int bf = it & 1;
        CP_WAIT0();
        __syncthreads();
        if (it + 1 < NT) load_tile((it + 1) * 128, (it + 1) & 1);

        const uint32_t sbK = sb + bf * BUFSZ;
        const uint32_t sbV = sbK + 2 * KBYTES;

        float s[64];
#pragma unroll
        for (int i = 0; i < 64; i++) s[i] = 0.f;
        uint32_t pr[32];

        auto softmax_block = [&](int ks) {
            float p0 = ex2f(s[ks * 8 + 0] * cexp);
            float p1 = ex2f(s[ks * 8 + 1] * cexp);
            float p2 = ex2f(s[ks * 8 + 2] * cexp);
            float p3 = ex2f(s[ks * 8 + 3] * cexp);
            float p4 = ex2f(s[ks * 8 + 4] * cexp);
            float p5 = ex2f(s[ks * 8 + 5] * cexp);
            float p6 = ex2f(s[ks * 8 + 6] * cexp);
            float p7 = ex2f(s[ks * 8 + 7] * cexp);
            lsum_lo += (p0 + p1) + (p4 + p5);
            lsum_hi += (p2 + p3) + (p6 + p7);
            pr[ks * 4 + 0] = cvthf2(p0, p1);
            pr[ks * 4 + 1] = cvthf2(p2, p3);
            pr[ks * 4 + 2] = cvthf2(p4, p5);
            pr[ks * 4 + 3] = cvthf2(p6, p7);
        };

        // S = (Qhi+Qlo)(Khi+Klo)^T, 3 first-order terms; softmax interleaved
#pragma unroll
        for (int nb2 = 0; nb2 < 8; nb2++) {
#pragma unroll
            for (int ks = 0; ks < 4; ks++) {
                uint32_t a = sbK + (uint32_t)((nb2 * 16 + (mm >> 1) * 8 + rr) * KSTRB +
                                              ks * 32 + (mm & 1) * 16);
                uint32_t kh[4], kl[4];
                ldsm4(a, kh);
                ldsm4(a + KBYTES, kl);
                mma_bf16(&s[nb2 * 8 + 0], &qh[ks * 4], kh[0], kh[1]);
                mma_bf16(&s[nb2 * 8 + 4], &qh[ks * 4], kh[2], kh[3]);
                mma_bf16(&s[nb2 * 8 + 0], &qh[ks * 4], kl[0], kl[1]);
                mma_bf16(&s[nb2 * 8 + 4], &qh[ks * 4], kl[2], kl[3]);
                mma_bf16(&s[nb2 * 8 + 0], &ql[ks * 4], kh[0], kh[1]);
                mma_bf16(&s[nb2 * 8 + 4], &ql[ks * 4], kh[2], kh[3]);
            }
            if (nb2 > 0) softmax_block(nb2 - 1);
        }
        softmax_block(7);

        // O += P @ V, single fp16 term
#pragma unroll
        for (int nb2 = 0; nb2 < 4; nb2++) {
#pragma unroll
            for (int ks = 0; ks < 8; ks++) {
                uint32_t a = sbV + (uint32_t)((nb2 * 16 + (mm >> 1) * 8 + rr) * VSTRB +
                                              ks * 32 + (mm & 1) * 16);
                uint32_t vh[4];
                ldsm4(a, vh);
                mma_fp16(&oacc[nb2 * 8 + 0], &pr[ks * 4], vh[0], vh[1]);
                mma_fp16(&oacc[nb2 * 8 + 4], &pr[ks * 4], vh[2], vh[3]);
            }
        }
    }

    lsum_lo += __shfl_xor_sync(0xffffffffu, lsum_lo, 1);
    lsum_lo += __shfl_xor_sync(0xffffffffu, lsum_lo, 2);
    lsum_hi += __shfl_xor_sync(0xffffffffu, lsum_hi, 1);
    lsum_hi += __shfl_xor_sync(0xffffffffu, lsum_hi, 2);
    float ilo = 1.0f / lsum_lo;
    float ihi = 1.0f / lsum_hi;

    const int row_lo = m0 + w * 16 + gid;
    const size_t ob = ((size_t)(b * SEQ + row_lo)) * DIMC + h * 64 + 2 * tg;
#pragma unroll
    for (int nb = 0; nb < 8; nb++) {
        float o0 = oacc[nb * 4 + 0] * ilo, o1 = oacc[nb * 4 + 1] * ilo;
        float h0 = bfr(o0), h1 = bfr(o1);
        *(uint32_t*)&ath[ob + nb * 8] = cvtbf2(h0, h1);
        *(uint32_t*)&atl[ob + nb * 8] = cvtbf2(o0 - h0, o1 - h1);
        float o2 = oacc[nb * 4 + 2] * ihi, o3 = oacc[nb * 4 + 3] * ihi;
        float h2 = bfr(o2), h3 = bfr(o3);
        *(uint32_t*)&ath[ob + 8 * DIMC + nb * 8] = cvtbf2(h2, h3);
        *(uint32_t*)&atl[ob + 8 * DIMC + nb * 8] = cvtbf2(o2 - h2, o3 - h3);
    }
}

// ---------------------------------------------------------------------------
extern "C" void kernel_launch(void* const* d_in, const int* in_sizes, int n_in,
                              void* d_out, int out_size) {
    const float* x      = (const float*)d_in[0];
    const float* w_qkv  = (const float*)d_in[1];
    const float* w_proj = (const float*)d_in[2];
    const float* b_proj = (const float*)d_in[3];
    float* out = (float*)d_out;

    void *xh, *xl, *wqh, *wql, *wph, *wpl, *oh, *ol, *vth, *ath, *atl;
    cudaGetSymbolAddress(&xh, g_xh);   cudaGetSymbolAddress(&xl, g_xl);
    cudaGetSymbolAddress(&wqh, g_wqh); cudaGetSymbolAddress(&wql, g_wql);
    cudaGetSymbolAddress(&wph, g_wph); cudaGetSymbolAddress(&wpl, g_wpl);
    cudaGetSymbolAddress(&oh, g_oh);   cudaGetSymbolAddress(&ol, g_ol);
    cudaGetSymbolAddress(&vth, g_vth);
    cudaGetSymbolAddress(&ath, g_ath); cudaGetSymbolAddress(&atl, g_atl);

    typedef __nv_bfloat16 bf;

    cudaFuncSetAttribute(flash_mma,
                         cudaFuncAttributeMaxDynamicSharedMemorySize, FL_SMEM);
    cudaFuncSetAttribute(gemm_tc<false>,
                         cudaFuncAttributeMaxDynamicSharedMemorySize, GEMM_SMEM);
    cudaFuncSetAttribute(gemm_tc<true>,
                         cudaFuncAttributeMaxDynamicSharedMemorySize, GEMM_SMEM);

    // 1) splits
    split_x<<<MROWS * DIMC / 4 / 256, 256>>>(x, (bf*)xh, (bf*)xl);
    split_wT<<<dim3(QKVC / 32, DIMC / 32), 256>>>(w_qkv, QKVC, (bf*)wqh, (bf*)wql);
    split_wT<<<dim3(DIMC / 32, DIMC / 32), 256>>>(w_proj, DIMC, (bf*)wph, (bf*)wpl);

    // 2) QKV projection (tensor) -> segmented q|k|v hi/lo
    gemm_tc<false><<<dim3(QKVC / 64, MROWS / 128), 256, GEMM_SMEM>>>(
        (const bf*)xh, (const bf*)xl, (const bf*)wqh, (const bf*)wql,
        nullptr, (bf*)oh, (bf*)ol, nullptr);

    // 3) V transpose -> fp16
    transpose_v<<<dim3(SEQ / 128, NHEADS, BATCH), 256>>>(
        (const bf*)oh + 2 * (size_t)SEGSZ, (const bf*)ol + 2 * (size_t)SEGSZ,
        (__half*)vth);

    // 4) flash attention -> att bf16 hi/lo
    flash_mma<<<dim3(SEQ / 128, NHEADS, BATCH), 256, FL_SMEM>>>(
        (const bf*)oh, (const bf*)ol,
        (const bf*)oh + (size_t)SEGSZ, (const bf*)ol + (size_t)SEGSZ,
        (const __half*)vth, (bf*)ath, (bf*)atl);

    // 5) output projection (tensor) + bias -> fp32 out
    gemm_tc<true><<<dim3(DIMC / 64, MROWS / 128), 256, GEMM_SMEM>>>(
        (const bf*)ath, (const bf*)atl, (const bf*)wph, (const bf*)wpl,
        b_proj, nullptr, nullptr, out);
}

// round 13
// speedup vs baseline: 1.8548x; 1.1938x over previous
#include <cuda_runtime.h>
#include <cuda_bf16.h>
#include <cuda_fp16.h>
#include <cstdint>

#define DIMC   512
#define NHEADS 8
#define HDIM   64
#define BATCH  2
#define SEQ    4096
#define MROWS  (BATCH * SEQ)     // 8192
#define QKVC   (3 * DIMC)        // 1536
#define SEGSZ  (MROWS * DIMC)    // 4194304

typedef unsigned long long u64;

// ------------------------- scratch (device globals) -------------------------
__device__ __nv_bfloat16 g_xh[MROWS * DIMC];
__device__ __nv_bfloat16 g_xl[MROWS * DIMC];
__device__ __nv_bfloat16 g_wqh[QKVC * DIMC];
__device__ __nv_bfloat16 g_wql[QKVC * DIMC];
__device__ __nv_bfloat16 g_wph[DIMC * DIMC];
__device__ __nv_bfloat16 g_wpl[DIMC * DIMC];
__device__ __half        g_oh[3 * SEGSZ];     // q | k | v  (token-major, fp16 hi)
__device__ __half        g_ol[3 * SEGSZ];     // q | k | v  (token-major, fp16 lo)
__device__ __half        g_vth[SEGSZ];        // V transposed [b][h][d][tok], fp16
__device__ __nv_bfloat16 g_ath[SEGSZ];        // attention out hi (bf16)
__device__ __nv_bfloat16 g_atl[SEGSZ];        // attention out lo (bf16)

// ------------------------------ helpers ------------------------------------
__device__ __forceinline__ uint32_t smem_u32(const void* p) {
    uint32_t a;
    asm("{ .reg .u64 t; cvta.to.shared.u64 t, %1; cvt.u32.u64 %0, t; }"
        : "=r"(a) : "l"(p));
    return a;
}
__device__ __forceinline__ float ex2f(float x) {
    float r; asm("ex2.approx.ftz.f32 %0, %1;" : "=f"(r) : "f"(x)); return r;
}
// pack 2 floats -> bf16x2 (first arg in low half)
__device__ __forceinline__ uint32_t cvtbf2(float lo, float hi) {
    uint32_t r;
    asm("cvt.rn.bf16x2.f32 %0, %1, %2;" : "=r"(r) : "f"(hi), "f"(lo));
    return r;
}
// pack 2 floats -> f16x2 (first arg in low half)
__device__ __forceinline__ uint32_t cvthf2(float lo, float hi) {
    uint32_t r;
    asm("cvt.rn.f16x2.f32 %0, %1, %2;" : "=r"(r) : "f"(hi), "f"(lo));
    return r;
}
__device__ __forceinline__ float bfr(float x) {   // round to bf16, back to f32
    return __bfloat162float(__float2bfloat16(x));
}
__device__ __forceinline__ float hfr(float x) {   // round to fp16, back to f32
    return __half2float(__float2half_rn(x));
}
// warp mma: D(16x8,f32) += A(16x16) * B(16x8)
__device__ __forceinline__ void mma_bf16(float* c, const uint32_t* a,
                                         uint32_t b0, uint32_t b1) {
    asm volatile("mma.sync.aligned.m16n8k16.row.col.f32.bf16.bf16.f32 "
        "{%0,%1,%2,%3}, {%4,%5,%6,%7}, {%8,%9}, {%0,%1,%2,%3};"
        : "+f"(c[0]), "+f"(c[1]), "+f"(c[2]), "+f"(c[3])
        : "r"(a[0]), "r"(a[1]), "r"(a[2]), "r"(a[3]), "r"(b0), "r"(b1));
}
__device__ __forceinline__ void mma_fp16(float* c, const uint32_t* a,
                                         uint32_t b0, uint32_t b1) {
    asm volatile("mma.sync.aligned.m16n8k16.row.col.f32.f16.f16.f32 "
        "{%0,%1,%2,%3}, {%4,%5,%6,%7}, {%8,%9}, {%0,%1,%2,%3};"
        : "+f"(c[0]), "+f"(c[1]), "+f"(c[2]), "+f"(c[3])
        : "r"(a[0]), "r"(a[1]), "r"(a[2]), "r"(a[3]), "r"(b0), "r"(b1));
}
__device__ __forceinline__ void ldsm4(uint32_t addr, uint32_t* d) {
    asm volatile("ldmatrix.sync.aligned.m8n8.x4.shared.b16 {%0,%1,%2,%3}, [%4];"
        : "=r"(d[0]), "=r"(d[1]), "=r"(d[2]), "=r"(d[3]) : "r"(addr));
}
__device__ __forceinline__ void cpasync16(uint32_t s, const void* g) {
    asm volatile("cp.async.cg.shared.global [%0], [%1], 16;" :: "r"(s), "l"(g));
}
#define CP_COMMIT() asm volatile("cp.async.commit_group;" ::: "memory")
#define CP_WAIT0()  asm volatile("cp.async.wait_group 0;" ::: "memory")

// ---------------------------------------------------------------------------
// split_x: fp32 -> bf16 hi/lo
// ---------------------------------------------------------------------------
__global__ __launch_bounds__(256)
void split_x(const float* __restrict__ x,
             __nv_bfloat16* __restrict__ xh, __nv_bfloat16* __restrict__ xl) {
    size_t i = ((size_t)blockIdx.x * 256 + threadIdx.x) * 4;
    float4 v = *(const float4*)&x[i];
    float h0 = bfr(v.x), h1 = bfr(v.y), h2 = bfr(v.z), h3 = bfr(v.w);
    *(uint2*)&xh[i] = make_uint2(cvtbf2(h0, h1), cvtbf2(h2, h3));
    *(uint2*)&xl[i] = make_uint2(cvtbf2(v.x - h0, v.y - h1),
                                 cvtbf2(v.z - h2, v.w - h3));
}

// ---------------------------------------------------------------------------
// split_wT: w[K=512][N] fp32 -> wT[N][512] bf16 hi/lo (transpose + split)
// ---------------------------------------------------------------------------
__global__ __launch_bounds__(256)
void split_wT(const float* __restrict__ w, int N,
              __nv_bfloat16* __restrict__ wth, __nv_bfloat16* __restrict__ wtl) {
    __shared__ float t[32][33];
    const int tid = threadIdx.x;
    const int n0 = blockIdx.x * 32, k0 = blockIdx.y * 32;
    int r = tid >> 3, cq = (tid & 7) * 4;
    float4 v = *(const float4*)&w[(size_t)(k0 + r) * N + n0 + cq];
    t[r][cq + 0] = v.x; t[r][cq + 1] = v.y;
    t[r][cq + 2] = v.z; t[r][cq + 3] = v.w;
    __syncthreads();
    int nr = tid >> 3, kq = (tid & 7) * 4;
    float v0 = t[kq + 0][nr], v1 = t[kq + 1][nr];
    float v2 = t[kq + 2][nr], v3 = t[kq + 3][nr];
    float h0 = bfr(v0), h1 = bfr(v1), h2 = bfr(v2), h3 = bfr(v3);
    size_t o = (size_t)(n0 + nr) * DIMC + k0 + kq;
    *(uint2*)&wth[o] = make_uint2(cvtbf2(h0, h1), cvtbf2(h2, h3));
    *(uint2*)&wtl[o] = make_uint2(cvtbf2(v0 - h0, v1 - h1),
                                  cvtbf2(v2 - h2, v3 - h3));
}

// ---------------------------------------------------------------------------
// gemm_tc: C[M,N] = (Ahi+Alo)[M,512] @ (Bhi+Blo)[512,N], 3 bf16 terms.
// EXACT R10/R12 structure (2-stage double buffer).
// PROJ=false: split result to *fp16* hi/lo segmented q|k|v.
// PROJ=true:  add bias, write fp32.
// ---------------------------------------------------------------------------
#define SA_STR 80                  // bytes/row: 32 bf16 + 16B pad
#define ATILE2 (128 * SA_STR)      // 10240
#define BTILE2 (64 * SA_STR)       // 5120
#define GBUF2  (2 * ATILE2 + 2 * BTILE2)   // 30720
#define GEMM_SMEM (2 * GBUF2)      // 61440

template <bool PROJ>
__global__ __launch_bounds__(256, 2)
void gemm_tc(const __nv_bfloat16* __restrict__ Ahi, const __nv_bfloat16* __restrict__ Alo,
             const __nv_bfloat16* __restrict__ BThi, const __nv_bfloat16* __restrict__ BTlo,
             const float* __restrict__ bias,
             __half* __restrict__ oh, __half* __restrict__ ol,
             float* __restrict__ outF) {
    extern __shared__ char smem[];
    const uint32_t sb = smem_u32(smem);
    const int tid = threadIdx.x;
    const int w = tid >> 5, lid = tid & 31;
    const int gid = lid >> 2, tg = lid & 3;
    const int mm = lid >> 3, rr = lid & 7;
    const int wm = w >> 1, wn = w & 1;
    const int bm = blockIdx.y * 128, bn = blockIdx.x * 64;

    auto load_chunk = [&](int k0, int bf) {
        uint32_t s0 = sb + bf * GBUF2;
#pragma unroll
        for (int l = 0; l < 2; l++) {
            int c = tid + l * 256;
            int row = c >> 2, kc = c & 3;
            uint32_t so = s0 + (uint32_t)(row * SA_STR + kc * 16);
            size_t ga = (size_t)(bm + row) * DIMC + k0 + kc * 8;
            cpasync16(so, Ahi + ga);
            cpasync16(so + ATILE2, Alo + ga);
        }
        {
            int row = tid >> 2, kc = tid & 3;
            uint32_t so = s0 + 2 * ATILE2 + (uint32_t)(row * SA_STR + kc * 16);
            size_t gb = (size_t)(bn + row) * DIMC + k0 + kc * 8;
            cpasync16(so, BThi + gb);
            cpasync16(so + BTILE2, BTlo + gb);
        }
        CP_COMMIT();
    };

    float acc[2][4][4];
#pragma unroll
    for (int i = 0; i < 2; i++)
#pragma unroll
        for (int j = 0; j < 4; j++)
#pragma unroll
            for (int q = 0; q < 4; q++) acc[i][j][q] = 0.f;

    load_chunk(0, 0);

    const int NC = DIMC / 32;   // 16
    for (int kc = 0; kc < NC; kc++) {
        const int bf = kc & 1;
        CP_WAIT0();
        __syncthreads();
        if (kc + 1 < NC) load_chunk((kc + 1) * 32, (kc + 1) & 1);

        const uint32_t sA = sb + bf * GBUF2;
        const uint32_t sB = sA + 2 * ATILE2;
#pragma unroll
        for (int kk = 0; kk < 2; kk++) {
            uint32_t ah[2][4], al[2][4];
#pragma unroll
            for (int i = 0; i < 2; i++) {
                uint32_t a = sA + (uint32_t)((wm * 32 + i * 16 + (mm & 1) * 8 + rr) * SA_STR +
                                             kk * 32 + (mm >> 1) * 16);
                ldsm4(a, ah[i]);
                ldsm4(a + ATILE2, al[i]);
            }
#pragma unroll
            for (int jb = 0; jb < 2; jb++) {
                uint32_t bh[4], bl[4];
                uint32_t a = sB + (uint32_t)((wn * 32 + jb * 16 + (mm >> 1) * 8 + rr) * SA_STR +
                                             kk * 32 + (mm & 1) * 16);
                ldsm4(a, bh);
                ldsm4(a + BTILE2, bl);
#pragma unroll
                for (int i = 0; i < 2; i++) {
                    mma_bf16(acc[i][2 * jb],     ah[i], bh[0], bh[1]);
                    mma_bf16(acc[i][2 * jb + 1], ah[i], bh[2], bh[3]);
                    mma_bf16(acc[i][2 * jb],     ah[i], bl[0], bl[1]);
                    mma_bf16(acc[i][2 * jb + 1], ah[i], bl[2], bl[3]);
                    mma_bf16(acc[i][2 * jb],     al[i], bh[0], bh[1]);
                    mma_bf16(acc[i][2 * jb + 1], al[i], bh[2], bh[3]);
                }
            }
        }
    }

    if (PROJ) {
#pragma unroll
        for (int i = 0; i < 2; i++) {
            int r = bm + wm * 32 + i * 16 + gid;
#pragma unroll
            for (int j = 0; j < 4; j++) {
                int c = bn + wn * 32 + j * 8 + 2 * tg;
                float b0 = bias[c], b1 = bias[c + 1];
                *(float2*)&outF[(size_t)r * DIMC + c] =
                    make_float2(acc[i][j][0] + b0, acc[i][j][1] + b1);
                *(float2*)&outF[(size_t)(r + 8) * DIMC + c] =
                    make_float2(acc[i][j][2] + b0, acc[i][j][3] + b1);
            }
        }
    } else {
        const int seg = bn >> 9;
        const size_t so = (size_t)seg * SEGSZ;
        const int cb = (bn & 511) + wn * 32;
#pragma unroll
        for (int i = 0; i < 2; i++) {
            int r = bm + wm * 32 + i * 16 + gid;
#pragma unroll
            for (int j = 0; j < 4; j++) {
                int c = cb + j * 8 + 2 * tg;
                float v0 = acc[i][j][0], v1 = acc[i][j][1];
                float v2 = acc[i][j][2], v3 = acc[i][j][3];
                float h0 = hfr(v0), h1 = hfr(v1), h2 = hfr(v2), h3 = hfr(v3);
                *(uint32_t*)&oh[so + (size_t)r * DIMC + c] = cvthf2(h0, h1);
                *(uint32_t*)&ol[so + (size_t)r * DIMC + c] = cvthf2(v0 - h0, v1 - h1);
                *(uint32_t*)&oh[so + (size_t)(r + 8) * DIMC + c] = cvthf2(h2, h3);
                *(uint32_t*)&ol[so + (size_t)(r + 8) * DIMC + c] = cvthf2(v2 - h2, v3 - h3);
            }
        }
    }
}

// ---------------------------------------------------------------------------
// transpose_v: fp16 hi/lo [b*tok][512] -> fp16 [b][h][d][SEQ] (v = hi + lo)
// ---------------------------------------------------------------------------
__global__ __launch_bounds__(256)
void transpose_v(const __half* __restrict__ vh, const __half* __restrict__ vl,
                 __half* __restrict__ vt) {
    __shared__ float t[64][129];
    const int tid = threadIdx.x;
    const int tt = blockIdx.x, h = blockIdx.y, b = blockIdx.z;
    const int tok0 = tt * 128;
    const size_t ibase = ((size_t)(b * SEQ + tok0)) * DIMC + h * 64;
    const size_t obase = ((size_t)((b * NHEADS + h) * HDIM)) * SEQ + tok0;

#pragma unroll
    for (int l = 0; l < 16; l++) {
        int idx = tid + l * 256;                 // 4096 = 128 tok x 32 du
        int tok = idx >> 5, du = idx & 31;
        uint32_t uh = *(const uint32_t*)(vh + ibase + (size_t)tok * DIMC + 2 * du);
        uint32_t ul = *(const uint32_t*)(vl + ibase + (size_t)tok * DIMC + 2 * du);
        float f0 = __half2float(((__half*)&uh)[0]) + __half2float(((__half*)&ul)[0]);
        float f1 = __half2float(((__half*)&uh)[1]) + __half2float(((__half*)&ul)[1]);
        t[2 * du + 0][tok] = f0;
        t[2 * du + 1][tok] = f1;
    }
    __syncthreads();
#pragma unroll
    for (int l = 0; l < 4; l++) {
        int idx = tid + l * 256;                 // 1024 = 64 d x 16 chunks
        int d = idx >> 4, tq = (idx & 15) * 8;
        uint4 o;
        o.x = cvthf2(t[d][tq + 0], t[d][tq + 1]);
        o.y = cvthf2(t[d][tq + 2], t[d][tq + 3]);
        o.z = cvthf2(t[d][tq + 4], t[d][tq + 5]);
        o.w = cvthf2(t[d][tq + 6], t[d][tq + 7]);
        *(uint4*)(vt + obase + (size_t)d * SEQ + tq) = o;
    }
}

// ---------------------------------------------------------------------------
// mma.sync flash attention. S = fp16 2-term (Q exact hi/lo x K hi);
// PV = single fp16. K-lo tile eliminated from SMEM.
// ---------------------------------------------------------------------------
#define KSTRB  144
#define VSTRB  272
#define KBYTES (128 * KSTRB)           // 18432
#define VBYTES (64 * VSTRB)            // 17408
#define BUFSZ  (KBYTES + VBYTES)       // 35840
#define FL_SMEM (2 * BUFSZ)            // 71680

__global__ __launch_bounds__(256, 1)
void flash_mma(const __half* __restrict__ qhi, const __half* __restrict__ qlo,
               const __half* __restrict__ khi,
               const __half* __restrict__ vt,
               __nv_bfloat16* __restrict__ ath, __nv_bfloat16* __restrict__ atl) {
    extern __shared__ char smem[];
    const uint32_t sb = smem_u32(smem);
    const int tid = threadIdx.x;
    const int w = tid >> 5, lid = tid & 31;
    const int gid = lid >> 2, tg = lid & 3;
    const int mm = lid >> 3, rr = lid & 7;
    const int m0 = blockIdx.x * 128, h = blockIdx.y, b = blockIdx.z;

    auto load_tile = [&](int n0, int bf) {
        uint32_t sk = sb + bf * BUFSZ;
        size_t kb = ((size_t)(b * SEQ + n0)) * DIMC + h * 64;
#pragma unroll
        for (int l = 0; l < 4; l++) {
            int c = tid + l * 256;
            int row = c >> 3, c8 = c & 7;
            uint32_t so = sk + (uint32_t)(row * KSTRB + c8 * 16);
            cpasync16(so, khi + kb + (size_t)row * DIMC + c8 * 8);
        }
        uint32_t sv = sk + KBYTES;
        size_t vb = ((size_t)((b * NHEADS + h) * HDIM)) * SEQ + n0;
#pragma unroll
        for (int l = 0; l < 4; l++) {
            int c = tid + l * 256;
            int d = c >> 4, kc = c & 15;
            uint32_t so = sv + (uint32_t)(d * VSTRB + kc * 16);
            cpasync16(so, vt + vb + (size_t)d * SEQ + kc * 8);
        }
        CP_COMMIT();
    };

    load_tile(0, 0);

    uint32_t qh[16], ql[16];
    {
        const size_t qb = ((size_t)(b * SEQ + m0 + w * 16 + gid)) * DIMC + h * 64;
#pragma unroll
        for (int ks = 0; ks < 4; ks++) {
            qh[ks * 4 + 0] = *(const uint32_t*)(qhi + qb + ks * 16 + 2 * tg);
            qh[ks * 4 + 1] = *(const uint32_t*)(qhi + qb + 8 * DIMC + ks * 16 + 2 * tg);
            qh[ks * 4 + 2] = *(const uint32_t*)(qhi + qb + ks * 16 + 8 + 2 * tg);
            qh[ks * 4 + 3] = *(const uint32_t*)(qhi + qb + 8 * DIMC + ks * 16 + 8 + 2 * tg);
            ql[ks * 4 + 0] = *(const uint32_t*)(qlo + qb + ks * 16 + 2 * tg);
            ql[ks * 4 + 1] = *(const uint32_t*)(qlo + qb + 8 * DIMC + ks * 16 + 2 * tg);
            ql[ks * 4 + 2] = *(const uint32_t*)(qlo + qb + ks * 16 + 8 + 2 * tg);
            ql[ks * 4 + 3] = *(const uint32_t*)(qlo + qb + 8 * DIMC + ks * 16 + 8 + 2 * tg);
        }
    }

    float oacc[32];
#pragma unroll
    for (int i = 0; i < 32; i++) oacc[i] = 0.f;
    float lsum_lo = 0.f, lsum_hi = 0.f;
    const float cexp = 0.125f * 1.4426950408889634f;

    const int NT = SEQ / 128;
    for (int it = 0; it < NT; it++) {
        const int bf = it & 1;
        CP_WAIT0();
        __syncthreads();
        if (it + 1 < NT) load_tile((it + 1) * 128, (it + 1) & 1);

        const uint32_t sbK = sb + bf * BUFSZ;
        const uint32_t sbV = sbK + KBYTES;

        float s[64];
#pragma unroll
        for (int i = 0; i < 64; i++) s[i] = 0.f;
        uint32_t pr[32];

        auto softmax_block = [&](int ks) {
            float p0 = ex2f(s[ks * 8 + 0] * cexp);
            float p1 = ex2f(s[ks * 8 + 1] * cexp);
            float p2 = ex2f(s[ks * 8 + 2] * cexp);
            float p3 = ex2f(s[ks * 8 + 3] * cexp);
            float p4 = ex2f(s[ks * 8 + 4] * cexp);
            float p5 = ex2f(s[ks * 8 + 5] * cexp);
            float p6 = ex2f(s[ks * 8 + 6] * cexp);
            float p7 = ex2f(s[ks * 8 + 7] * cexp);
            lsum_lo += (p0 + p1) + (p4 + p5);
            lsum_hi += (p2 + p3) + (p6 + p7);
            pr[ks * 4 + 0] = cvthf2(p0, p1);
            pr[ks * 4 + 1] = cvthf2(p2, p3);
            pr[ks * 4 + 2] = cvthf2(p4, p5);
            pr[ks * 4 + 3] = cvthf2(p6, p7);
        };

        // S = (Qhi+Qlo) @ Khi^T, 2 fp16 terms; softmax interleaved
#pragma unroll
        for (int nb2 = 0; nb2 < 8; nb2++) {
#pragma unroll
            for (int ks = 0; ks < 4; ks++) {
                uint32_t a = sbK + (uint32_t)((nb2 * 16 + (mm >> 1) * 8 + rr) * KSTRB +
                                              ks * 32 + (mm & 1) * 16);
                uint32_t kh[4];
                ldsm4(a, kh);
                mma_fp16(&s[nb2 * 8 + 0], &qh[ks * 4], kh[0], kh[1]);
                mma_fp16(&s[nb2 * 8 + 4], &qh[ks * 4], kh[2], kh[3]);
                mma_fp16(&s[nb2 * 8 + 0], &ql[ks * 4], kh[0], kh[1]);
                mma_fp16(&s[nb2 * 8 + 4], &ql[ks * 4], kh[2], kh[3]);
            }
            if (nb2 > 0) softmax_block(nb2 - 1);
        }
        softmax_block(7);

        // O += P @ V, single fp16 term
#pragma unroll
        for (int nb2 = 0; nb2 < 4; nb2++) {
#pragma unroll
            for (int ks = 0; ks < 8; ks++) {
                uint32_t a = sbV + (uint32_t)((nb2 * 16 + (mm >> 1) * 8 + rr) * VSTRB +
                                              ks * 32 + (mm & 1) * 16);
                uint32_t vh[4];
                ldsm4(a, vh);
                mma_fp16(&oacc[nb2 * 8 + 0], &pr[ks * 4], vh[0], vh[1]);
                mma_fp16(&oacc[nb2 * 8 + 4], &pr[ks * 4], vh[2], vh[3]);
            }
        }
    }

    lsum_lo += __shfl_xor_sync(0xffffffffu, lsum_lo, 1);
    lsum_lo += __shfl_xor_sync(0xffffffffu, lsum_lo, 2);
    lsum_hi += __shfl_xor_sync(0xffffffffu, lsum_hi, 1);
    lsum_hi += __shfl_xor_sync(0xffffffffu, lsum_hi, 2);
    float ilo = 1.0f / lsum_lo;
    float ihi = 1.0f / lsum_hi;

    const int row_lo = m0 + w * 16 + gid;
    const size_t ob = ((size_t)(b * SEQ + row_lo)) * DIMC + h * 64 + 2 * tg;
#pragma unroll
    for (int nb = 0; nb < 8; nb++) {
        float o0 = oacc[nb * 4 + 0] * ilo, o1 = oacc[nb * 4 + 1] * ilo;
        float h0 = bfr(o0), h1 = bfr(o1);
        *(uint32_t*)&ath[ob + nb * 8] = cvtbf2(h0, h1);
        *(uint32_t*)&atl[ob + nb * 8] = cvtbf2(o0 - h0, o1 - h1);
        float o2 = oacc[nb * 4 + 2] * ihi, o3 = oacc[nb * 4 + 3] * ihi;
        float h2 = bfr(o2), h3 = bfr(o3);
        *(uint32_t*)&ath[ob + 8 * DIMC + nb * 8] = cvtbf2(h2, h3);
        *(uint32_t*)&atl[ob + 8 * DIMC + nb * 8] = cvtbf2(o2 - h2, o3 - h3);
    }
}

// ---------------------------------------------------------------------------
extern "C" void kernel_launch(void* const* d_in, const int* in_sizes, int n_in,
                              void* d_out, int out_size) {
    const float* x      = (const float*)d_in[0];
    const float* w_qkv  = (const float*)d_in[1];
    const float* w_proj = (const float*)d_in[2];
    const float* b_proj = (const float*)d_in[3];
    float* out = (float*)d_out;

    void *xh, *xl, *wqh, *wql, *wph, *wpl, *oh, *ol, *vth, *ath, *atl;
    cudaGetSymbolAddress(&xh, g_xh);   cudaGetSymbolAddress(&xl, g_xl);
    cudaGetSymbolAddress(&wqh, g_wqh); cudaGetSymbolAddress(&wql, g_wql);
    cudaGetSymbolAddress(&wph, g_wph); cudaGetSymbolAddress(&wpl, g_wpl);
    cudaGetSymbolAddress(&oh, g_oh);   cudaGetSymbolAddress(&ol, g_ol);
    cudaGetSymbolAddress(&vth, g_vth);
    cudaGetSymbolAddress(&ath, g_ath); cudaGetSymbolAddress(&atl, g_atl);

    typedef __nv_bfloat16 bf;
    typedef __half hf;

    cudaFuncSetAttribute(flash_mma,
                         cudaFuncAttributeMaxDynamicSharedMemorySize, FL_SMEM);
    cudaFuncSetAttribute(gemm_tc<false>,
                         cudaFuncAttributeMaxDynamicSharedMemorySize, GEMM_SMEM);
    cudaFuncSetAttribute(gemm_tc<true>,
                         cudaFuncAttributeMaxDynamicSharedMemorySize, GEMM_SMEM);

    // 1) splits
    split_x<<<MROWS * DIMC / 4 / 256, 256>>>(x, (bf*)xh, (bf*)xl);
    split_wT<<<dim3(QKVC / 32, DIMC / 32), 256>>>(w_qkv, QKVC, (bf*)wqh, (bf*)wql);
    split_wT<<<dim3(DIMC / 32, DIMC / 32), 256>>>(w_proj, DIMC, (bf*)wph, (bf*)wpl);

    // 2) QKV projection (tensor) -> segmented q|k|v fp16 hi/lo
    gemm_tc<false><<<dim3(QKVC / 64, MROWS / 128), 256, GEMM_SMEM>>>(
        (const bf*)xh, (const bf*)xl, (const bf*)wqh, (const bf*)wql,
        nullptr, (hf*)oh, (hf*)ol, nullptr);

    // 3) V transpose -> fp16
    transpose_v<<<dim3(SEQ / 128, NHEADS, BATCH), 256>>>(
        (const hf*)oh + 2 * (size_t)SEGSZ, (const hf*)ol + 2 * (size_t)SEGSZ,
        (hf*)vth);

    // 4) flash attention -> att bf16 hi/lo
    flash_mma<<<dim3(SEQ / 128, NHEADS, BATCH), 256, FL_SMEM>>>(
        (const hf*)oh, (const hf*)ol,
        (const hf*)oh + (size_t)SEGSZ,
        (const hf*)vth, (bf*)ath, (bf*)atl);

    // 5) output projection (tensor) + bias -> fp32 out
    gemm_tc<true><<<dim3(DIMC / 64, MROWS / 128), 256, GEMM_SMEM>>>(
        (const bf*)ath, (const bf*)atl, (const bf*)wph, (const bf*)wpl,
        b_proj, nullptr, nullptr, out);
}

// round 14
// speedup vs baseline: 2.2627x; 1.2199x over previous
#include <cuda_runtime.h>
#include <cuda_bf16.h>
#include <cuda_fp16.h>
#include <cstdint>

#define DIMC   512
#define NHEADS 8
#define HDIM   64
#define BATCH  2
#define SEQ    4096
#define MROWS  (BATCH * SEQ)     // 8192
#define QKVC   (3 * DIMC)        // 1536
#define SEGSZ  (MROWS * DIMC)    // 4194304

typedef unsigned long long u64;

// ------------------------- scratch (device globals) -------------------------
__device__ __half g_xh[MROWS * DIMC];         // x fp16 hi
__device__ __half g_xl[MROWS * DIMC];         // x fp16 lo
__device__ __half g_wq[QKVC * DIMC];          // w_qkv^T fp16 (hi only)
__device__ __half g_wp[DIMC * DIMC];          // w_proj^T fp16 (hi only)
__device__ __half g_oh[3 * SEGSZ];            // q | k | v  fp16 hi
__device__ __half g_ol[3 * SEGSZ];            // q | k | v  fp16 lo
__device__ __half g_vth[SEGSZ];               // V transposed [b][h][d][tok]
__device__ __half g_ath[SEGSZ];               // attention out fp16 hi
__device__ __half g_atl[SEGSZ];               // attention out fp16 lo

// ------------------------------ helpers ------------------------------------
__device__ __forceinline__ uint32_t smem_u32(const void* p) {
    uint32_t a;
    asm("{ .reg .u64 t; cvta.to.shared.u64 t, %1; cvt.u32.u64 %0, t; }"
        : "=r"(a) : "l"(p));
    return a;
}
__device__ __forceinline__ float ex2f(float x) {
    float r; asm("ex2.approx.ftz.f32 %0, %1;" : "=f"(r) : "f"(x)); return r;
}
// pack 2 floats -> f16x2 (first arg in low half)
__device__ __forceinline__ uint32_t cvthf2(float lo, float hi) {
    uint32_t r;
    asm("cvt.rn.f16x2.f32 %0, %1, %2;" : "=r"(r) : "f"(hi), "f"(lo));
    return r;
}
__device__ __forceinline__ float hfr(float x) {   // round to fp16, back to f32
    return __half2float(__float2half_rn(x));
}
// warp mma: D(16x8,f32) += A(16x16,f16) * B(16x8,f16)
__device__ __forceinline__ void mma_fp16(float* c, const uint32_t* a,
                                         uint32_t b0, uint32_t b1) {
    asm volatile("mma.sync.aligned.m16n8k16.row.col.f32.f16.f16.f32 "
        "{%0,%1,%2,%3}, {%4,%5,%6,%7}, {%8,%9}, {%0,%1,%2,%3};"
        : "+f"(c[0]), "+f"(c[1]), "+f"(c[2]), "+f"(c[3])
        : "r"(a[0]), "r"(a[1]), "r"(a[2]), "r"(a[3]), "r"(b0), "r"(b1));
}
__device__ __forceinline__ void ldsm4(uint32_t addr, uint32_t* d) {
    asm volatile("ldmatrix.sync.aligned.m8n8.x4.shared.b16 {%0,%1,%2,%3}, [%4];"
        : "=r"(d[0]), "=r"(d[1]), "=r"(d[2]), "=r"(d[3]) : "r"(addr));
}
__device__ __forceinline__ void cpasync16(uint32_t s, const void* g) {
    asm volatile("cp.async.cg.shared.global [%0], [%1], 16;" :: "r"(s), "l"(g));
}
#define CP_COMMIT() asm volatile("cp.async.commit_group;" ::: "memory")
#define CP_WAIT0()  asm volatile("cp.async.wait_group 0;" ::: "memory")

// ---------------------------------------------------------------------------
// split_x: fp32 -> fp16 hi/lo (hi+lo exact to ~2^-22)
// ---------------------------------------------------------------------------
__global__ __launch_bounds__(256)
void split_x(const float* __restrict__ x,
             __half* __restrict__ xh, __half* __restrict__ xl) {
    size_t i = ((size_t)blockIdx.x * 256 + threadIdx.x) * 4;
    float4 v = *(const float4*)&x[i];
    float h0 = hfr(v.x), h1 = hfr(v.y), h2 = hfr(v.z), h3 = hfr(v.w);
    *(uint2*)&xh[i] = make_uint2(cvthf2(h0, h1), cvthf2(h2, h3));
    *(uint2*)&xl[i] = make_uint2(cvthf2(v.x - h0, v.y - h1),
                                 cvthf2(v.z - h2, v.w - h3));
}

// ---------------------------------------------------------------------------
// split_wT: w[K=512][N] fp32 -> wT[N][512] fp16 (hi only; transpose)
// ---------------------------------------------------------------------------
__global__ __launch_bounds__(256)
void split_wT(const float* __restrict__ w, int N, __half* __restrict__ wt) {
    __shared__ float t[32][33];
    const int tid = threadIdx.x;
    const int n0 = blockIdx.x * 32, k0 = blockIdx.y * 32;
    int r = tid >> 3, cq = (tid & 7) * 4;
    float4 v = *(const float4*)&w[(size_t)(k0 + r) * N + n0 + cq];
    t[r][cq + 0] = v.x; t[r][cq + 1] = v.y;
    t[r][cq + 2] = v.z; t[r][cq + 3] = v.w;
    __syncthreads();
    int nr = tid >> 3, kq = (tid & 7) * 4;
    size_t o = (size_t)(n0 + nr) * DIMC + k0 + kq;
    *(uint2*)&wt[o] = make_uint2(cvthf2(t[kq + 0][nr], t[kq + 1][nr]),
                                 cvthf2(t[kq + 2][nr], t[kq + 3][nr]));
}

// ---------------------------------------------------------------------------
// gemm_tc: C[M,N] = (Ahi+Alo)[M,512] @ Bhi[512,N], 2 fp16 terms.
// Same R10 skeleton: CTA 128x64, BK=32, 2-stage buffer, 8 warps (4x2),
// warp 32x32, 2 CTAs/SM. B-lo tile eliminated.
// ---------------------------------------------------------------------------
#define SA_STR 80                  // bytes/row: 32 halves + 16B pad
#define ATILE2 (128 * SA_STR)      // 10240
#define BTILE2 (64 * SA_STR)       // 5120
#define GBUF2  (2 * ATILE2 + BTILE2)   // 25600
#define GEMM_SMEM (2 * GBUF2)      // 51200

template <bool PROJ>
__global__ __launch_bounds__(256, 2)
void gemm_tc(const __half* __restrict__ Ahi, const __half* __restrict__ Alo,
             const __half* __restrict__ BT,
             const float* __restrict__ bias,
             __half* __restrict__ oh, __half* __restrict__ ol,
             float* __restrict__ outF) {
    extern __shared__ char smem[];
    const uint32_t sb = smem_u32(smem);
    const int tid = threadIdx.x;
    const int w = tid >> 5, lid = tid & 31;
    const int gid = lid >> 2, tg = lid & 3;
    const int mm = lid >> 3, rr = lid & 7;
    const int wm = w >> 1, wn = w & 1;
    const int bm = blockIdx.y * 128, bn = blockIdx.x * 64;

    auto load_chunk = [&](int k0, int bf) {
        uint32_t s0 = sb + bf * GBUF2;
#pragma unroll
        for (int l = 0; l < 2; l++) {
            int c = tid + l * 256;
            int row = c >> 2, kc = c & 3;
            uint32_t so = s0 + (uint32_t)(row * SA_STR + kc * 16);
            size_t ga = (size_t)(bm + row) * DIMC + k0 + kc * 8;
            cpasync16(so, Ahi + ga);
            cpasync16(so + ATILE2, Alo + ga);
        }
        {
            int row = tid >> 2, kc = tid & 3;
            uint32_t so = s0 + 2 * ATILE2 + (uint32_t)(row * SA_STR + kc * 16);
            cpasync16(so, BT + (size_t)(bn + row) * DIMC + k0 + kc * 8);
        }
        CP_COMMIT();
    };

    float acc[2][4][4];
#pragma unroll
    for (int i = 0; i < 2; i++)
#pragma unroll
        for (int j = 0; j < 4; j++)
#pragma unroll
            for (int q = 0; q < 4; q++) acc[i][j][q] = 0.f;

    load_chunk(0, 0);

    const int NC = DIMC / 32;   // 16
    for (int kc = 0; kc < NC; kc++) {
        const int bf = kc & 1;
        CP_WAIT0();
        __syncthreads();
        if (kc + 1 < NC) load_chunk((kc + 1) * 32, (kc + 1) & 1);

        const uint32_t sA = sb + bf * GBUF2;
        const uint32_t sB = sA + 2 * ATILE2;
#pragma unroll
        for (int kk = 0; kk < 2; kk++) {
            uint32_t ah[2][4], al[2][4];
#pragma unroll
            for (int i = 0; i < 2; i++) {
                uint32_t a = sA + (uint32_t)((wm * 32 + i * 16 + (mm & 1) * 8 + rr) * SA_STR +
                                             kk * 32 + (mm >> 1) * 16);
                ldsm4(a, ah[i]);
                ldsm4(a + ATILE2, al[i]);
            }
#pragma unroll
            for (int jb = 0; jb < 2; jb++) {
                uint32_t bh[4];
                uint32_t a = sB + (uint32_t)((wn * 32 + jb * 16 + (mm >> 1) * 8 + rr) * SA_STR +
                                             kk * 32 + (mm & 1) * 16);
                ldsm4(a, bh);
#pragma unroll
                for (int i = 0; i < 2; i++) {
                    mma_fp16(acc[i][2 * jb],     ah[i], bh[0], bh[1]);
                    mma_fp16(acc[i][2 * jb + 1], ah[i], bh[2], bh[3]);
                    mma_fp16(acc[i][2 * jb],     al[i], bh[0], bh[1]);
                    mma_fp16(acc[i][2 * jb + 1], al[i], bh[2], bh[3]);
                }
            }
        }
    }

    if (PROJ) {
#pragma unroll
        for (int i = 0; i < 2; i++) {
            int r = bm + wm * 32 + i * 16 + gid;
#pragma unroll
            for (int j = 0; j < 4; j++) {
                int c = bn + wn * 32 + j * 8 + 2 * tg;
                float b0 = bias[c], b1 = bias[c + 1];
                *(float2*)&outF[(size_t)r * DIMC + c] =
                    make_float2(acc[i][j][0] + b0, acc[i][j][1] + b1);
                *(float2*)&outF[(size_t)(r + 8) * DIMC + c] =
                    make_float2(acc[i][j][2] + b0, acc[i][j][3] + b1);
            }
        }
    } else {
        const int seg = bn >> 9;
        const size_t so = (size_t)seg * SEGSZ;
        const int cb = (bn & 511) + wn * 32;
#pragma unroll
        for (int i = 0; i < 2; i++) {
            int r = bm + wm * 32 + i * 16 + gid;
#pragma unroll
            for (int j = 0; j < 4; j++) {
                int c = cb + j * 8 + 2 * tg;
                float v0 = acc[i][j][0], v1 = acc[i][j][1];
                float v2 = acc[i][j][2], v3 = acc[i][j][3];
                float h0 = hfr(v0), h1 = hfr(v1), h2 = hfr(v2), h3 = hfr(v3);
                *(uint32_t*)&oh[so + (size_t)r * DIMC + c] = cvthf2(h0, h1);
                *(uint32_t*)&ol[so + (size_t)r * DIMC + c] = cvthf2(v0 - h0, v1 - h1);
                *(uint32_t*)&oh[so + (size_t)(r + 8) * DIMC + c] = cvthf2(h2, h3);
                *(uint32_t*)&ol[so + (size_t)(r + 8) * DIMC + c] = cvthf2(v2 - h2, v3 - h3);
            }
        }
    }
}

// ---------------------------------------------------------------------------
// transpose_v: fp16 hi/lo [b*tok][512] -> fp16 [b][h][d][SEQ] (v = hi + lo)
// ---------------------------------------------------------------------------
__global__ __launch_bounds__(256)
void transpose_v(const __half* __restrict__ vh, const __half* __restrict__ vl,
                 __half* __restrict__ vt) {
    __shared__ float t[64][129];
    const int tid = threadIdx.x;
    const int tt = blockIdx.x, h = blockIdx.y, b = blockIdx.z;
    const int tok0 = tt * 128;
    const size_t ibase = ((size_t)(b * SEQ + tok0)) * DIMC + h * 64;
    const size_t obase = ((size_t)((b * NHEADS + h) * HDIM)) * SEQ + tok0;

#pragma unroll
    for (int l = 0; l < 16; l++) {
        int idx = tid + l * 256;                 // 4096 = 128 tok x 32 du
        int tok = idx >> 5, du = idx & 31;
        uint32_t uh = *(const uint32_t*)(vh + ibase + (size_t)tok * DIMC + 2 * du);
        uint32_t ul = *(const uint32_t*)(vl + ibase + (size_t)tok * DIMC + 2 * du);
        float f0 = __half2float(((__half*)&uh)[0]) + __half2float(((__half*)&ul)[0]);
        float f1 = __half2float(((__half*)&uh)[1]) + __half2float(((__half*)&ul)[1]);
        t[2 * du + 0][tok] = f0;
        t[2 * du + 1][tok] = f1;
    }
    __syncthreads();
#pragma unroll
    for (int l = 0; l < 4; l++) {
        int idx = tid + l * 256;                 // 1024 = 64 d x 16 chunks
        int d = idx >> 4, tq = (idx & 15) * 8;
        uint4 o;
        o.x = cvthf2(t[d][tq + 0], t[d][tq + 1]);
        o.y = cvthf2(t[d][tq + 2], t[d][tq + 3]);
        o.z = cvthf2(t[d][tq + 4], t[d][tq + 5]);
        o.w = cvthf2(t[d][tq + 6], t[d][tq + 7]);
        *(uint4*)(vt + obase + (size_t)d * SEQ + tq) = o;
    }
}

// ---------------------------------------------------------------------------
// mma.sync flash attention. S = single fp16 term (Qhi x Khi);
// PV = single fp16. 128 MMAs/tile total.
// ---------------------------------------------------------------------------
#define KSTRB  144
#define VSTRB  272
#define KBYTES (128 * KSTRB)           // 18432
#define VBYTES (64 * VSTRB)            // 17408
#define BUFSZ  (KBYTES + VBYTES)       // 35840
#define FL_SMEM (2 * BUFSZ)            // 71680

__global__ __launch_bounds__(256, 1)
void flash_mma(const __half* __restrict__ qhi,
               const __half* __restrict__ khi,
               const __half* __restrict__ vt,
               __half* __restrict__ ath, __half* __restrict__ atl) {
    extern __shared__ char smem[];
    const uint32_t sb = smem_u32(smem);
    const int tid = threadIdx.x;
    const int w = tid >> 5, lid = tid & 31;
    const int gid = lid >> 2, tg = lid & 3;
    const int mm = lid >> 3, rr = lid & 7;
    const int m0 = blockIdx.x * 128, h = blockIdx.y, b = blockIdx.z;

    auto load_tile = [&](int n0, int bf) {
        uint32_t sk = sb + bf * BUFSZ;
        size_t kb = ((size_t)(b * SEQ + n0)) * DIMC + h * 64;
#pragma unroll
        for (int l = 0; l < 4; l++) {
            int c = tid + l * 256;
            int row = c >> 3, c8 = c & 7;
            uint32_t so = sk + (uint32_t)(row * KSTRB + c8 * 16);
            cpasync16(so, khi + kb + (size_t)row * DIMC + c8 * 8);
        }
        uint32_t sv = sk + KBYTES;
        size_t vb = ((size_t)((b * NHEADS + h) * HDIM)) * SEQ + n0;
#pragma unroll
        for (int l = 0; l < 4; l++) {
            int c = tid + l * 256;
            int d = c >> 4, kc = c & 15;
            uint32_t so = sv + (uint32_t)(d * VSTRB + kc * 16);
            cpasync16(so, vt + vb + (size_t)d * SEQ + kc * 8);
        }
        CP_COMMIT();
    };

    load_tile(0, 0);

    uint32_t qh[16];
    {
        const size_t qb = ((size_t)(b * SEQ + m0 + w * 16 + gid)) * DIMC + h * 64;
#pragma unroll
        for (int ks = 0; ks < 4; ks++) {
            qh[ks * 4 + 0] = *(const uint32_t*)(qhi + qb + ks * 16 + 2 * tg);
            qh[ks * 4 + 1] = *(const uint32_t*)(qhi + qb + 8 * DIMC + ks * 16 + 2 * tg);
            qh[ks * 4 + 2] = *(const uint32_t*)(qhi + qb + ks * 16 + 8 + 2 * tg);
            qh[ks * 4 + 3] = *(const uint32_t*)(qhi + qb + 8 * DIMC + ks * 16 + 8 + 2 * tg);
        }
    }

    float oacc[32];
#pragma unroll
    for (int i = 0; i < 32; i++) oacc[i] = 0.f;
    float lsum_lo = 0.f, lsum_hi = 0.f;
    const float cexp = 0.125f * 1.4426950408889634f;

    const int NT = SEQ / 128;
    for (int it = 0; it < NT; it++) {
        const int bf = it & 1;
        CP_WAIT0();
        __syncthreads();
        if (it + 1 < NT) load_tile((it + 1) * 128, (it + 1) & 1);

        const uint32_t sbK = sb + bf * BUFSZ;
        const uint32_t sbV = sbK + KBYTES;

        float s[64];
#pragma unroll
        for (int i = 0; i < 64; i++) s[i] = 0.f;
        uint32_t pr[32];

        auto softmax_block = [&](int ks) {
            float p0 = ex2f(s[ks * 8 + 0] * cexp);
            float p1 = ex2f(s[ks * 8 + 1] * cexp);
            float p2 = ex2f(s[ks * 8 + 2] * cexp);
            float p3 = ex2f(s[ks * 8 + 3] * cexp);
            float p4 = ex2f(s[ks * 8 + 4] * cexp);
            float p5 = ex2f(s[ks * 8 + 5] * cexp);
            float p6 = ex2f(s[ks * 8 + 6] * cexp);
            float p7 = ex2f(s[ks * 8 + 7] * cexp);
            lsum_lo += (p0 + p1) + (p4 + p5);
            lsum_hi += (p2 + p3) + (p6 + p7);
            pr[ks * 4 + 0] = cvthf2(p0, p1);
            pr[ks * 4 + 1] = cvthf2(p2, p3);
            pr[ks * 4 + 2] = cvthf2(p4, p5);
            pr[ks * 4 + 3] = cvthf2(p6, p7);
        };

        // S = Qhi @ Khi^T, single fp16 term; softmax interleaved
#pragma unroll
        for (int nb2 = 0; nb2 < 8; nb2++) {
#pragma unroll
            for (int ks = 0; ks < 4; ks++) {
                uint32_t a = sbK + (uint32_t)((nb2 * 16 + (mm >> 1) * 8 + rr) * KSTRB +
                                              ks * 32 + (mm & 1) * 16);
                uint32_t kh[4];
                ldsm4(a, kh);
                mma_fp16(&s[nb2 * 8 + 0], &qh[ks * 4], kh[0], kh[1]);
                mma_fp16(&s[nb2 * 8 + 4], &qh[ks * 4], kh[2], kh[3]);
            }
            if (nb2 > 0) softmax_block(nb2 - 1);
        }
        softmax_block(7);

        // O += P @ V, single fp16 term
#pragma unroll
        for (int nb2 = 0; nb2 < 4; nb2++) {
#pragma unroll
            for (int ks = 0; ks < 8; ks++) {
                uint32_t a = sbV + (uint32_t)((nb2 * 16 + (mm >> 1) * 8 + rr) * VSTRB +
                                              ks * 32 + (mm & 1) * 16);
                uint32_t vh[4];
                ldsm4(a, vh);
                mma_fp16(&oacc[nb2 * 8 + 0], &pr[ks * 4], vh[0], vh[1]);
                mma_fp16(&oacc[nb2 * 8 + 4], &pr[ks * 4], vh[2], vh[3]);
            }
        }
    }

    lsum_lo += __shfl_xor_sync(0xffffffffu, lsum_lo, 1);
    lsum_lo += __shfl_xor_sync(0xffffffffu, lsum_lo, 2);
    lsum_hi += __shfl_xor_sync(0xffffffffu, lsum_hi, 1);
    lsum_hi += __shfl_xor_sync(0xffffffffu, lsum_hi, 2);
    float ilo = 1.0f / lsum_lo;
    float ihi = 1.0f / lsum_hi;

    const int row_lo = m0 + w * 16 + gid;
    const size_t ob = ((size_t)(b * SEQ + row_lo)) * DIMC + h * 64 + 2 * tg;
#pragma unroll
    for (int nb = 0; nb < 8; nb++) {
        float o0 = oacc[nb * 4 + 0] * ilo, o1 = oacc[nb * 4 + 1] * ilo;
        float h0 = hfr(o0), h1 = hfr(o1);
        *(uint32_t*)&ath[ob + nb * 8] = cvthf2(h0, h1);
        *(uint32_t*)&atl[ob + nb * 8] = cvthf2(o0 - h0, o1 - h1);
        float o2 = oacc[nb * 4 + 2] * ihi, o3 = oacc[nb * 4 + 3] * ihi;
        float h2 = hfr(o2), h3 = hfr(o3);
        *(uint32_t*)&ath[ob + 8 * DIMC + nb * 8] = cvthf2(h2, h3);
        *(uint32_t*)&atl[ob + 8 * DIMC + nb * 8] = cvthf2(o2 - h2, o3 - h3);
    }
}

// ---------------------------------------------------------------------------
extern "C" void kernel_launch(void* const* d_in, const int* in_sizes, int n_in,
                              void* d_out, int out_size) {
    const float* x      = (const float*)d_in[0];
    const float* w_qkv  = (const float*)d_in[1];
    const float* w_proj = (const float*)d_in[2];
    const float* b_proj = (const float*)d_in[3];
    float* out = (float*)d_out;

    void *xh, *xl, *wq, *wp, *oh, *ol, *vth, *ath, *atl;
    cudaGetSymbolAddress(&xh, g_xh);   cudaGetSymbolAddress(&xl, g_xl);
    cudaGetSymbolAddress(&wq, g_wq);   cudaGetSymbolAddress(&wp, g_wp);
    cudaGetSymbolAddress(&oh, g_oh);   cudaGetSymbolAddress(&ol, g_ol);
    cudaGetSymbolAddress(&vth, g_vth);
    cudaGetSymbolAddress(&ath, g_ath); cudaGetSymbolAddress(&atl, g_atl);

    typedef __half hf;

    cudaFuncSetAttribute(flash_mma,
                         cudaFuncAttributeMaxDynamicSharedMemorySize, FL_SMEM);
    cudaFuncSetAttribute(gemm_tc<false>,
                         cudaFuncAttributeMaxDynamicSharedMemorySize, GEMM_SMEM);
    cudaFuncSetAttribute(gemm_tc<true>,
                         cudaFuncAttributeMaxDynamicSharedMemorySize, GEMM_SMEM);

    // 1) splits (x -> fp16 hi/lo; weights -> fp16 hi, transposed)
    split_x<<<MROWS * DIMC / 4 / 256, 256>>>(x, (hf*)xh, (hf*)xl);
    split_wT<<<dim3(QKVC / 32, DIMC / 32), 256>>>(w_qkv, QKVC, (hf*)wq);
    split_wT<<<dim3(DIMC / 32, DIMC / 32), 256>>>(w_proj, DIMC, (hf*)wp);

    // 2) QKV projection (fp16 2-term) -> segmented q|k|v fp16 hi/lo
    gemm_tc<false><<<dim3(QKVC / 64, MROWS / 128), 256, GEMM_SMEM>>>(
        (const hf*)xh, (const hf*)xl, (const hf*)wq,
        nullptr, (hf*)oh, (hf*)ol, nullptr);

    // 3) V transpose -> fp16
    transpose_v<<<dim3(SEQ / 128, NHEADS, BATCH), 256>>>(
        (const hf*)oh + 2 * (size_t)SEGSZ, (const hf*)ol + 2 * (size_t)SEGSZ,
        (hf*)vth);

    // 4) flash attention -> att fp16 hi/lo
    flash_mma<<<dim3(SEQ / 128, NHEADS, BATCH), 256, FL_SMEM>>>(
        (const hf*)oh, (const hf*)oh + (size_t)SEGSZ,
        (const hf*)vth, (hf*)ath, (hf*)atl);

    // 5) output projection (fp16 2-term) + bias -> fp32 out
    gemm_tc<true><<<dim3(DIMC / 64, MROWS / 128), 256, GEMM_SMEM>>>(
        (const hf*)ath, (const hf*)atl, (const hf*)wp,
        b_proj, nullptr, nullptr, out);
}

// round 15
// speedup vs baseline: 2.5232x; 1.1151x over previous
#include <cuda_runtime.h>
#include <cuda_bf16.h>
#include <cuda_fp16.h>
#include <cstdint>

#define DIMC   512
#define NHEADS 8
#define HDIM   64
#define BATCH  2
#define SEQ    4096
#define MROWS  (BATCH * SEQ)     // 8192
#define QKVC   (3 * DIMC)        // 1536
#define SEGSZ  (MROWS * DIMC)    // 4194304
#define CEXP   0.18033688011112042f   // 0.125 * log2(e)

typedef unsigned long long u64;

// ------------------------- scratch (device globals) -------------------------
__device__ __half g_xh[MROWS * DIMC];         // x fp16 hi
__device__ __half g_xl[MROWS * DIMC];         // x fp16 lo
__device__ __half g_wq[QKVC * DIMC];          // w_qkv^T fp16 (hi only)
__device__ __half g_wp[DIMC * DIMC];          // w_proj^T fp16 (hi only)
__device__ __half g_oh[3 * SEGSZ];            // q | k | v  fp16 hi (q pre-scaled by CEXP)
__device__ __half g_ol[3 * SEGSZ];            // q | k | v  fp16 lo
__device__ __half g_vth[SEGSZ];               // V transposed [b][h][d][tok]
__device__ __half g_ath[SEGSZ];               // attention out fp16 hi
__device__ __half g_atl[SEGSZ];               // attention out fp16 lo

// ------------------------------ helpers ------------------------------------
__device__ __forceinline__ uint32_t smem_u32(const void* p) {
    uint32_t a;
    asm("{ .reg .u64 t; cvta.to.shared.u64 t, %1; cvt.u32.u64 %0, t; }"
        : "=r"(a) : "l"(p));
    return a;
}
__device__ __forceinline__ float ex2f(float x) {
    float r; asm("ex2.approx.ftz.f32 %0, %1;" : "=f"(r) : "f"(x)); return r;
}
// pack 2 floats -> f16x2 (first arg in low half)
__device__ __forceinline__ uint32_t cvthf2(float lo, float hi) {
    uint32_t r;
    asm("cvt.rn.f16x2.f32 %0, %1, %2;" : "=r"(r) : "f"(hi), "f"(lo));
    return r;
}
__device__ __forceinline__ float hfr(float x) {   // round to fp16, back to f32
    return __half2float(__float2half_rn(x));
}
// warp mma: D(16x8,f32) += A(16x16,f16) * B(16x8,f16)
__device__ __forceinline__ void mma_fp16(float* c, const uint32_t* a,
                                         uint32_t b0, uint32_t b1) {
    asm volatile("mma.sync.aligned.m16n8k16.row.col.f32.f16.f16.f32 "
        "{%0,%1,%2,%3}, {%4,%5,%6,%7}, {%8,%9}, {%0,%1,%2,%3};"
        : "+f"(c[0]), "+f"(c[1]), "+f"(c[2]), "+f"(c[3])
        : "r"(a[0]), "r"(a[1]), "r"(a[2]), "r"(a[3]), "r"(b0), "r"(b1));
}
__device__ __forceinline__ void ldsm4(uint32_t addr, uint32_t* d) {
    asm volatile("ldmatrix.sync.aligned.m8n8.x4.shared.b16 {%0,%1,%2,%3}, [%4];"
        : "=r"(d[0]), "=r"(d[1]), "=r"(d[2]), "=r"(d[3]) : "r"(addr));
}
__device__ __forceinline__ void cpasync16(uint32_t s, const void* g) {
    asm volatile("cp.async.cg.shared.global [%0], [%1], 16;" :: "r"(s), "l"(g));
}
#define CP_COMMIT() asm volatile("cp.async.commit_group;" ::: "memory")
#define CP_WAIT0()  asm volatile("cp.async.wait_group 0;" ::: "memory")

// ---------------------------------------------------------------------------
// split_x: fp32 -> fp16 hi/lo (hi+lo exact to ~2^-22)
// ---------------------------------------------------------------------------
__global__ __launch_bounds__(256)
void split_x(const float* __restrict__ x,
             __half* __restrict__ xh, __half* __restrict__ xl) {
    size_t i = ((size_t)blockIdx.x * 256 + threadIdx.x) * 4;
    float4 v = *(const float4*)&x[i];
    float h0 = hfr(v.x), h1 = hfr(v.y), h2 = hfr(v.z), h3 = hfr(v.w);
    *(uint2*)&xh[i] = make_uint2(cvthf2(h0, h1), cvthf2(h2, h3));
    *(uint2*)&xl[i] = make_uint2(cvthf2(v.x - h0, v.y - h1),
                                 cvthf2(v.z - h2, v.w - h3));
}

// ---------------------------------------------------------------------------
// split_wT: w[K=512][N] fp32 -> wT[N][512] fp16 (hi only; transpose)
// ---------------------------------------------------------------------------
__global__ __launch_bounds__(256)
void split_wT(const float* __restrict__ w, int N, __half* __restrict__ wt) {
    __shared__ float t[32][33];
    const int tid = threadIdx.x;
    const int n0 = blockIdx.x * 32, k0 = blockIdx.y * 32;
    int r = tid >> 3, cq = (tid & 7) * 4;
    float4 v = *(const float4*)&w[(size_t)(k0 + r) * N + n0 + cq];
    t[r][cq + 0] = v.x; t[r][cq + 1] = v.y;
    t[r][cq + 2] = v.z; t[r][cq + 3] = v.w;
    __syncthreads();
    int nr = tid >> 3, kq = (tid & 7) * 4;
    size_t o = (size_t)(n0 + nr) * DIMC + k0 + kq;
    *(uint2*)&wt[o] = make_uint2(cvthf2(t[kq + 0][nr], t[kq + 1][nr]),
                                 cvthf2(t[kq + 2][nr], t[kq + 3][nr]));
}

// ---------------------------------------------------------------------------
// gemm_tc: C[M,N] = (Ahi+Alo)[M,512] @ Bhi[512,N], 2 fp16 terms.
// BK=64 (8 barrier rounds instead of 16). CTA 128x64, 2-stage buffer,
// 8 warps (4x2), warp 32x32, 2 CTAs/SM.
// PROJ=false: split to fp16 hi/lo segmented q|k|v, Q segment pre-scaled CEXP.
// ---------------------------------------------------------------------------
#define SA_STR 144                 // bytes/row: 64 halves (128B) + 16B pad
#define ATILE2 (128 * SA_STR)      // 18432
#define BTILE2 (64 * SA_STR)       // 9216
#define GBUF2  (2 * ATILE2 + BTILE2)   // 46080
#define GEMM_SMEM (2 * GBUF2)      // 92160

template <bool PROJ>
__global__ __launch_bounds__(256, 2)
void gemm_tc(const __half* __restrict__ Ahi, const __half* __restrict__ Alo,
             const __half* __restrict__ BT,
             const float* __restrict__ bias,
             __half* __restrict__ oh, __half* __restrict__ ol,
             float* __restrict__ outF) {
    extern __shared__ char smem[];
    const uint32_t sb = smem_u32(smem);
    const int tid = threadIdx.x;
    const int w = tid >> 5, lid = tid & 31;
    const int gid = lid >> 2, tg = lid & 3;
    const int mm = lid >> 3, rr = lid & 7;
    const int wm = w >> 1, wn = w & 1;
    const int bm = blockIdx.y * 128, bn = blockIdx.x * 64;

    auto load_chunk = [&](int k0, int bf) {
        uint32_t s0 = sb + bf * GBUF2;
        // A: 128 rows x 8 kc = 1024 chunks per matrix (hi+lo)
#pragma unroll
        for (int l = 0; l < 4; l++) {
            int c = tid + l * 256;
            int row = c >> 3, kc = c & 7;
            uint32_t so = s0 + (uint32_t)(row * SA_STR + kc * 16);
            size_t ga = (size_t)(bm + row) * DIMC + k0 + kc * 8;
            cpasync16(so, Ahi + ga);
            cpasync16(so + ATILE2, Alo + ga);
        }
        // B: 64 rows x 8 kc = 512 chunks
#pragma unroll
        for (int l = 0; l < 2; l++) {
            int c = tid + l * 256;
            int row = c >> 3, kc = c & 7;
            uint32_t so = s0 + 2 * ATILE2 + (uint32_t)(row * SA_STR + kc * 16);
            cpasync16(so, BT + (size_t)(bn + row) * DIMC + k0 + kc * 8);
        }
        CP_COMMIT();
    };

    float acc[2][4][4];
#pragma unroll
    for (int i = 0; i < 2; i++)
#pragma unroll
        for (int j = 0; j < 4; j++)
#pragma unroll
            for (int q = 0; q < 4; q++) acc[i][j][q] = 0.f;

    load_chunk(0, 0);

    const int NC = DIMC / 64;   // 8
    for (int kc = 0; kc < NC; kc++) {
        const int bf = kc & 1;
        CP_WAIT0();
        __syncthreads();
        if (kc + 1 < NC) load_chunk((kc + 1) * 64, (kc + 1) & 1);

        const uint32_t sA = sb + bf * GBUF2;
        const uint32_t sB = sA + 2 * ATILE2;
#pragma unroll
        for (int kk = 0; kk < 4; kk++) {
            uint32_t ah[2][4], al[2][4];
#pragma unroll
            for (int i = 0; i < 2; i++) {
                uint32_t a = sA + (uint32_t)((wm * 32 + i * 16 + (mm & 1) * 8 + rr) * SA_STR +
                                             kk * 32 + (mm >> 1) * 16);
                ldsm4(a, ah[i]);
                ldsm4(a + ATILE2, al[i]);
            }
#pragma unroll
            for (int jb = 0; jb < 2; jb++) {
                uint32_t bh[4];
                uint32_t a = sB + (uint32_t)((wn * 32 + jb * 16 + (mm >> 1) * 8 + rr) * SA_STR +
                                             kk * 32 + (mm & 1) * 16);
                ldsm4(a, bh);
#pragma unroll
                for (int i = 0; i < 2; i++) {
                    mma_fp16(acc[i][2 * jb],     ah[i], bh[0], bh[1]);
                    mma_fp16(acc[i][2 * jb + 1], ah[i], bh[2], bh[3]);
                    mma_fp16(acc[i][2 * jb],     al[i], bh[0], bh[1]);
                    mma_fp16(acc[i][2 * jb + 1], al[i], bh[2], bh[3]);
                }
            }
        }
    }

    if (PROJ) {
#pragma unroll
        for (int i = 0; i < 2; i++) {
            int r = bm + wm * 32 + i * 16 + gid;
#pragma unroll
            for (int j = 0; j < 4; j++) {
                int c = bn + wn * 32 + j * 8 + 2 * tg;
                float b0 = bias[c], b1 = bias[c + 1];
                *(float2*)&outF[(size_t)r * DIMC + c] =
                    make_float2(acc[i][j][0] + b0, acc[i][j][1] + b1);
                *(float2*)&outF[(size_t)(r + 8) * DIMC + c] =
                    make_float2(acc[i][j][2] + b0, acc[i][j][3] + b1);
            }
        }
    } else {
        const int seg = bn >> 9;
        const float scale = (seg == 0) ? CEXP : 1.0f;   // fold softmax scale into Q
        const size_t so = (size_t)seg * SEGSZ;
        const int cb = (bn & 511) + wn * 32;
#pragma unroll
        for (int i = 0; i < 2; i++) {
            int r = bm + wm * 32 + i * 16 + gid;
#pragma unroll
            for (int j = 0; j < 4; j++) {
                int c = cb + j * 8 + 2 * tg;
                float v0 = acc[i][j][0] * scale, v1 = acc[i][j][1] * scale;
                float v2 = acc[i][j][2] * scale, v3 = acc[i][j][3] * scale;
                float h0 = hfr(v0), h1 = hfr(v1), h2 = hfr(v2), h3 = hfr(v3);
                *(uint32_t*)&oh[so + (size_t)r * DIMC + c] = cvthf2(h0, h1);
                *(uint32_t*)&ol[so + (size_t)r * DIMC + c] = cvthf2(v0 - h0, v1 - h1);
                *(uint32_t*)&oh[so + (size_t)(r + 8) * DIMC + c] = cvthf2(h2, h3);
                *(uint32_t*)&ol[so + (size_t)(r + 8) * DIMC + c] = cvthf2(v2 - h2, v3 - h3);
            }
        }
    }
}

// ---------------------------------------------------------------------------
// transpose_v: fp16 hi/lo [b*tok][512] -> fp16 [b][h][d][SEQ] (v = hi + lo)
// ---------------------------------------------------------------------------
__global__ __launch_bounds__(256)
void transpose_v(const __half* __restrict__ vh, const __half* __restrict__ vl,
                 __half* __restrict__ vt) {
    __shared__ float t[64][129];
    const int tid = threadIdx.x;
    const int tt = blockIdx.x, h = blockIdx.y, b = blockIdx.z;
    const int tok0 = tt * 128;
    const size_t ibase = ((size_t)(b * SEQ + tok0)) * DIMC + h * 64;
    const size_t obase = ((size_t)((b * NHEADS + h) * HDIM)) * SEQ + tok0;

#pragma unroll
    for (int l = 0; l < 16; l++) {
        int idx = tid + l * 256;                 // 4096 = 128 tok x 32 du
        int tok = idx >> 5, du = idx & 31;
        uint32_t uh = *(const uint32_t*)(vh + ibase + (size_t)tok * DIMC + 2 * du);
        uint32_t ul = *(const uint32_t*)(vl + ibase + (size_t)tok * DIMC + 2 * du);
        float f0 = __half2float(((__half*)&uh)[0]) + __half2float(((__half*)&ul)[0]);
        float f1 = __half2float(((__half*)&uh)[1]) + __half2float(((__half*)&ul)[1]);
        t[2 * du + 0][tok] = f0;
        t[2 * du + 1][tok] = f1;
    }
    __syncthreads();
#pragma unroll
    for (int l = 0; l < 4; l++) {
        int idx = tid + l * 256;                 // 1024 = 64 d x 16 chunks
        int d = idx >> 4, tq = (idx & 15) * 8;
        uint4 o;
        o.x = cvthf2(t[d][tq + 0], t[d][tq + 1]);
        o.y = cvthf2(t[d][tq + 2], t[d][tq + 3]);
        o.z = cvthf2(t[d][tq + 4], t[d][tq + 5]);
        o.w = cvthf2(t[d][tq + 6], t[d][tq + 7]);
        *(uint4*)(vt + obase + (size_t)d * SEQ + tq) = o;
    }
}

// ---------------------------------------------------------------------------
// mma.sync flash attention. 64-query CTAs, 128 threads (4 warps), so 2 CTAs
// co-reside per SM and cover each other's barrier/wait stalls.
// S = Qhi(pre-scaled) x Khi, PV = P x V, all single fp16 terms.
// ---------------------------------------------------------------------------
#define KSTRB  144
#define VSTRB  272
#define KBYTES (128 * KSTRB)           // 18432
#define VBYTES (64 * VSTRB)            // 17408
#define BUFSZ  (KBYTES + VBYTES)       // 35840
#define FL_SMEM (2 * BUFSZ)            // 71680

__global__ __launch_bounds__(128)
void flash_mma(const __half* __restrict__ qhi,
               const __half* __restrict__ khi,
               const __half* __restrict__ vt,
               __half* __restrict__ ath, __half* __restrict__ atl) {
    extern __shared__ char smem[];
    const uint32_t sb = smem_u32(smem);
    const int tid = threadIdx.x;
    const int w = tid >> 5, lid = tid & 31;
    const int gid = lid >> 2, tg = lid & 3;
    const int mm = lid >> 3, rr = lid & 7;
    const int m0 = blockIdx.x * 64, h = blockIdx.y, b = blockIdx.z;

    auto load_tile = [&](int n0, int bf) {
        uint32_t sk = sb + bf * BUFSZ;
        size_t kb = ((size_t)(b * SEQ + n0)) * DIMC + h * 64;
#pragma unroll
        for (int l = 0; l < 8; l++) {
            int c = tid + l * 128;               // 1024 K chunks
            int row = c >> 3, c8 = c & 7;
            uint32_t so = sk + (uint32_t)(row * KSTRB + c8 * 16);
            cpasync16(so, khi + kb + (size_t)row * DIMC + c8 * 8);
        }
        uint32_t sv = sk + KBYTES;
        size_t vb = ((size_t)((b * NHEADS + h) * HDIM)) * SEQ + n0;
#pragma unroll
        for (int l = 0; l < 8; l++) {
            int c = tid + l * 128;               // 1024 V chunks
            int d = c >> 4, kc = c & 15;
            uint32_t so = sv + (uint32_t)(d * VSTRB + kc * 16);
            cpasync16(so, vt + vb + (size_t)d * SEQ + kc * 8);
        }
        CP_COMMIT();
    };

    load_tile(0, 0);

    uint32_t qh[16];
    {
        const size_t qb = ((size_t)(b * SEQ + m0 + w * 16 + gid)) * DIMC + h * 64;
#pragma unroll
        for (int ks = 0; ks < 4; ks++) {
            qh[ks * 4 + 0] = *(const uint32_t*)(qhi + qb + ks * 16 + 2 * tg);
            qh[ks * 4 + 1] = *(const uint32_t*)(qhi + qb + 8 * DIMC + ks * 16 + 2 * tg);
            qh[ks * 4 + 2] = *(const uint32_t*)(qhi + qb + ks * 16 + 8 + 2 * tg);
            qh[ks * 4 + 3] = *(const uint32_t*)(qhi + qb + 8 * DIMC + ks * 16 + 8 + 2 * tg);
        }
    }

    float oacc[32];
#pragma unroll
    for (int i = 0; i < 32; i++) oacc[i] = 0.f;
    float lsum_lo = 0.f, lsum_hi = 0.f;

    const int NT = SEQ / 128;
    for (int it = 0; it < NT; it++) {
        const int bf = it & 1;
        CP_WAIT0();
        __syncthreads();
        if (it + 1 < NT) load_tile((it + 1) * 128, (it + 1) & 1);

        const uint32_t sbK = sb + bf * BUFSZ;
        const uint32_t sbV = sbK + KBYTES;

        float s[64];
#pragma unroll
        for (int i = 0; i < 64; i++) s[i] = 0.f;
        uint32_t pr[32];

        auto softmax_block = [&](int ks) {
            float p0 = ex2f(s[ks * 8 + 0]);
            float p1 = ex2f(s[ks * 8 + 1]);
            float p2 = ex2f(s[ks * 8 + 2]);
            float p3 = ex2f(s[ks * 8 + 3]);
            float p4 = ex2f(s[ks * 8 + 4]);
            float p5 = ex2f(s[ks * 8 + 5]);
            float p6 = ex2f(s[ks * 8 + 6]);
            float p7 = ex2f(s[ks * 8 + 7]);
            lsum_lo += (p0 + p1) + (p4 + p5);
            lsum_hi += (p2 + p3) + (p6 + p7);
            pr[ks * 4 + 0] = cvthf2(p0, p1);
            pr[ks * 4 + 1] = cvthf2(p2, p3);
            pr[ks * 4 + 2] = cvthf2(p4, p5);
            pr[ks * 4 + 3] = cvthf2(p6, p7);
        };

        // S = Qs @ Khi^T (Q carries the softmax scale); softmax interleaved
#pragma unroll
        for (int nb2 = 0; nb2 < 8; nb2++) {
#pragma unroll
            for (int ks = 0; ks < 4; ks++) {
                uint32_t a = sbK + (uint32_t)((nb2 * 16 + (mm >> 1) * 8 + rr) * KSTRB +
                                              ks * 32 + (mm & 1) * 16);
                uint32_t kh[4];
                ldsm4(a, kh);
                mma_fp16(&s[nb2 * 8 + 0], &qh[ks * 4], kh[0], kh[1]);
                mma_fp16(&s[nb2 * 8 + 4], &qh[ks * 4], kh[2], kh[3]);
            }
            if (nb2 > 0) softmax_block(nb2 - 1);
        }
        softmax_block(7);

        // O += P @ V
#pragma unroll
        for (int nb2 = 0; nb2 < 4; nb2++) {
#pragma unroll
            for (int ks = 0; ks < 8; ks++) {
                uint32_t a = sbV + (uint32_t)((nb2 * 16 + (mm >> 1) * 8 + rr) * VSTRB +
                                              ks * 32 + (mm & 1) * 16);
                uint32_t vh[4];
                ldsm4(a, vh);
                mma_fp16(&oacc[nb2 * 8 + 0], &pr[ks * 4], vh[0], vh[1]);
                mma_fp16(&oacc[nb2 * 8 + 4], &pr[ks * 4], vh[2], vh[3]);
            }
        }
    }

    lsum_lo += __shfl_xor_sync(0xffffffffu, lsum_lo, 1);
    lsum_lo += __shfl_xor_sync(0xffffffffu, lsum_lo, 2);
    lsum_hi += __shfl_xor_sync(0xffffffffu, lsum_hi, 1);
    lsum_hi += __shfl_xor_sync(0xffffffffu, lsum_hi, 2);
    float ilo = 1.0f / lsum_lo;
    float ihi = 1.0f / lsum_hi;

    const int row_lo = m0 + w * 16 + gid;
    const size_t ob = ((size_t)(b * SEQ + row_lo)) * DIMC + h * 64 + 2 * tg;
#pragma unroll
    for (int nb = 0; nb < 8; nb++) {
        float o0 = oacc[nb * 4 + 0] * ilo, o1 = oacc[nb * 4 + 1] * ilo;
        float h0 = hfr(o0), h1 = hfr(o1);
        *(uint32_t*)&ath[ob + nb * 8] = cvthf2(h0, h1);
        *(uint32_t*)&atl[ob + nb * 8] = cvthf2(o0 - h0, o1 - h1);
        float o2 = oacc[nb * 4 + 2] * ihi, o3 = oacc[nb * 4 + 3] * ihi;
        float h2 = hfr(o2), h3 = hfr(o3);
        *(uint32_t*)&ath[ob + 8 * DIMC + nb * 8] = cvthf2(h2, h3);
        *(uint32_t*)&atl[ob + 8 * DIMC + nb * 8] = cvthf2(o2 - h2, o3 - h3);
    }
}

// ---------------------------------------------------------------------------
extern "C" void kernel_launch(void* const* d_in, const int* in_sizes, int n_in,
                              void* d_out, int out_size) {
    const float* x      = (const float*)d_in[0];
    const float* w_qkv  = (const float*)d_in[1];
    const float* w_proj = (const float*)d_in[2];
    const float* b_proj = (const float*)d_in[3];
    float* out = (float*)d_out;

    void *xh, *xl, *wq, *wp, *oh, *ol, *vth, *ath, *atl;
    cudaGetSymbolAddress(&xh, g_xh);   cudaGetSymbolAddress(&xl, g_xl);
    cudaGetSymbolAddress(&wq, g_wq);   cudaGetSymbolAddress(&wp, g_wp);
    cudaGetSymbolAddress(&oh, g_oh);   cudaGetSymbolAddress(&ol, g_ol);
    cudaGetSymbolAddress(&vth, g_vth);
    cudaGetSymbolAddress(&ath, g_ath); cudaGetSymbolAddress(&atl, g_atl);

    typedef __half hf;

    cudaFuncSetAttribute(flash_mma,
                         cudaFuncAttributeMaxDynamicSharedMemorySize, FL_SMEM);
    cudaFuncSetAttribute(gemm_tc<false>,
                         cudaFuncAttributeMaxDynamicSharedMemorySize, GEMM_SMEM);
    cudaFuncSetAttribute(gemm_tc<true>,
                         cudaFuncAttributeMaxDynamicSharedMemorySize, GEMM_SMEM);

    // 1) splits (x -> fp16 hi/lo; weights -> fp16 hi, transposed)
    split_x<<<MROWS * DIMC / 4 / 256, 256>>>(x, (hf*)xh, (hf*)xl);
    split_wT<<<dim3(QKVC / 32, DIMC / 32), 256>>>(w_qkv, QKVC, (hf*)wq);
    split_wT<<<dim3(DIMC / 32, DIMC / 32), 256>>>(w_proj, DIMC, (hf*)wp);

    // 2) QKV projection (fp16 2-term, BK=64) -> q|k|v fp16 hi/lo (Q pre-scaled)
    gemm_tc<false><<<dim3(QKVC / 64, MROWS / 128), 256, GEMM_SMEM>>>(
        (const hf*)xh, (const hf*)xl, (const hf*)wq,
        nullptr, (hf*)oh, (hf*)ol, nullptr);

    // 3) V transpose -> fp16
    transpose_v<<<dim3(SEQ / 128, NHEADS, BATCH), 256>>>(
        (const hf*)oh + 2 * (size_t)SEGSZ, (const hf*)ol + 2 * (size_t)SEGSZ,
        (hf*)vth);

    // 4) flash attention (64-query CTAs, 128 thr) -> att fp16 hi/lo
    flash_mma<<<dim3(SEQ / 64, NHEADS, BATCH), 128, FL_SMEM>>>(
        (const hf*)oh, (const hf*)oh + (size_t)SEGSZ,
        (const hf*)vth, (hf*)ath, (hf*)atl);

    // 5) output projection (fp16 2-term, BK=64) + bias -> fp32 out
    gemm_tc<true><<<dim3(DIMC / 64, MROWS / 128), 256, GEMM_SMEM>>>(
        (const hf*)ath, (const hf*)atl, (const hf*)wp,
        b_proj, nullptr, nullptr, out);
}

// round 16
// speedup vs baseline: 2.7119x; 1.0748x over previous
#include <cuda_runtime.h>
#include <cuda_bf16.h>
#include <cuda_fp16.h>
#include <cstdint>

#define DIMC   512
#define NHEADS 8
#define HDIM   64
#define BATCH  2
#define SEQ    4096
#define MROWS  (BATCH * SEQ)     // 8192
#define QKVC   (3 * DIMC)        // 1536
#define SEGSZ  (MROWS * DIMC)    // 4194304
#define CEXP   0.18033688011112042f   // 0.125 * log2(e)

typedef unsigned long long u64;

// ------------------------- scratch (device globals) -------------------------
__device__ __half g_xh[MROWS * DIMC];         // x fp16 hi
__device__ __half g_xl[MROWS * DIMC];         // x fp16 lo
__device__ __half g_wq[QKVC * DIMC];          // w_qkv^T fp16 (hi only)
__device__ __half g_wp[DIMC * DIMC];          // w_proj^T fp16 (hi only)
__device__ __half g_oh[3 * SEGSZ];            // q | k | v fp16 (q pre-scaled by CEXP)
__device__ __half g_ath[SEGSZ];               // attention out fp16 hi
__device__ __half g_atl[SEGSZ];               // attention out fp16 lo

// ------------------------------ helpers ------------------------------------
__device__ __forceinline__ uint32_t smem_u32(const void* p) {
    uint32_t a;
    asm("{ .reg .u64 t; cvta.to.shared.u64 t, %1; cvt.u32.u64 %0, t; }"
        : "=r"(a) : "l"(p));
    return a;
}
__device__ __forceinline__ float ex2f(float x) {
    float r; asm("ex2.approx.ftz.f32 %0, %1;" : "=f"(r) : "f"(x)); return r;
}
// pack 2 floats -> f16x2 (first arg in low half)
__device__ __forceinline__ uint32_t cvthf2(float lo, float hi) {
    uint32_t r;
    asm("cvt.rn.f16x2.f32 %0, %1, %2;" : "=r"(r) : "f"(hi), "f"(lo));
    return r;
}
__device__ __forceinline__ float hfr(float x) {   // round to fp16, back to f32
    return __half2float(__float2half_rn(x));
}
// warp mma: D(16x8,f32) += A(16x16,f16) * B(16x8,f16)
__device__ __forceinline__ void mma_fp16(float* c, const uint32_t* a,
                                         uint32_t b0, uint32_t b1) {
    asm volatile("mma.sync.aligned.m16n8k16.row.col.f32.f16.f16.f32 "
        "{%0,%1,%2,%3}, {%4,%5,%6,%7}, {%8,%9}, {%0,%1,%2,%3};"
        : "+f"(c[0]), "+f"(c[1]), "+f"(c[2]), "+f"(c[3])
        : "r"(a[0]), "r"(a[1]), "r"(a[2]), "r"(a[3]), "r"(b0), "r"(b1));
}
__device__ __forceinline__ void ldsm4(uint32_t addr, uint32_t* d) {
    asm volatile("ldmatrix.sync.aligned.m8n8.x4.shared.b16 {%0,%1,%2,%3}, [%4];"
        : "=r"(d[0]), "=r"(d[1]), "=r"(d[2]), "=r"(d[3]) : "r"(addr));
}
__device__ __forceinline__ void ldsm4t(uint32_t addr, uint32_t* d) {
    asm volatile("ldmatrix.sync.aligned.m8n8.x4.trans.shared.b16 {%0,%1,%2,%3}, [%4];"
        : "=r"(d[0]), "=r"(d[1]), "=r"(d[2]), "=r"(d[3]) : "r"(addr));
}
__device__ __forceinline__ void cpasync16(uint32_t s, const void* g) {
    asm volatile("cp.async.cg.shared.global [%0], [%1], 16;" :: "r"(s), "l"(g));
}
#define CP_COMMIT() asm volatile("cp.async.commit_group;" ::: "memory")
#define CP_WAIT0()  asm volatile("cp.async.wait_group 0;" ::: "memory")

// ---------------------------------------------------------------------------
// split_x: fp32 -> fp16 hi/lo (hi+lo exact to ~2^-22)
// ---------------------------------------------------------------------------
__global__ __launch_bounds__(256)
void split_x(const float* __restrict__ x,
             __half* __restrict__ xh, __half* __restrict__ xl) {
    size_t i = ((size_t)blockIdx.x * 256 + threadIdx.x) * 4;
    float4 v = *(const float4*)&x[i];
    float h0 = hfr(v.x), h1 = hfr(v.y), h2 = hfr(v.z), h3 = hfr(v.w);
    *(uint2*)&xh[i] = make_uint2(cvthf2(h0, h1), cvthf2(h2, h3));
    *(uint2*)&xl[i] = make_uint2(cvthf2(v.x - h0, v.y - h1),
                                 cvthf2(v.z - h2, v.w - h3));
}

// ---------------------------------------------------------------------------
// split_wT: w[K=512][N] fp32 -> wT[N][512] fp16 (hi only; transpose)
// ---------------------------------------------------------------------------
__global__ __launch_bounds__(256)
void split_wT(const float* __restrict__ w, int N, __half* __restrict__ wt) {
    __shared__ float t[32][33];
    const int tid = threadIdx.x;
    const int n0 = blockIdx.x * 32, k0 = blockIdx.y * 32;
    int r = tid >> 3, cq = (tid & 7) * 4;
    float4 v = *(const float4*)&w[(size_t)(k0 + r) * N + n0 + cq];
    t[r][cq + 0] = v.x; t[r][cq + 1] = v.y;
    t[r][cq + 2] = v.z; t[r][cq + 3] = v.w;
    __syncthreads();
    int nr = tid >> 3, kq = (tid & 7) * 4;
    size_t o = (size_t)(n0 + nr) * DIMC + k0 + kq;
    *(uint2*)&wt[o] = make_uint2(cvthf2(t[kq + 0][nr], t[kq + 1][nr]),
                                 cvthf2(t[kq + 2][nr], t[kq + 3][nr]));
}

// ---------------------------------------------------------------------------
// gemm_tc: C[M,N] = (Ahi+Alo)[M,512] @ Bhi[512,N], 2 fp16 terms. BK=64,
// CTA 128x64, 2-stage buffer, 8 warps (4x2), warp 32x32, 2 CTAs/SM.
// PROJ=false: fp16 hi only -> segmented q|k|v (Q pre-scaled by CEXP).
// PROJ=true:  add bias, write fp32.
// ---------------------------------------------------------------------------
#define SA_STR 144                 // bytes/row: 64 halves (128B) + 16B pad
#define ATILE2 (128 * SA_STR)      // 18432
#define BTILE2 (64 * SA_STR)       // 9216
#define GBUF2  (2 * ATILE2 + BTILE2)   // 46080
#define GEMM_SMEM (2 * GBUF2)      // 92160

template <bool PROJ>
__global__ __launch_bounds__(256, 2)
void gemm_tc(const __half* __restrict__ Ahi, const __half* __restrict__ Alo,
             const __half* __restrict__ BT,
             const float* __restrict__ bias,
             __half* __restrict__ oh, __half* __restrict__ ol,
             float* __restrict__ outF) {
    extern __shared__ char smem[];
    const uint32_t sb = smem_u32(smem);
    const int tid = threadIdx.x;
    const int w = tid >> 5, lid = tid & 31;
    const int gid = lid >> 2, tg = lid & 3;
    const int mm = lid >> 3, rr = lid & 7;
    const int wm = w >> 1, wn = w & 1;
    const int bm = blockIdx.y * 128, bn = blockIdx.x * 64;

    auto load_chunk = [&](int k0, int bf) {
        uint32_t s0 = sb + bf * GBUF2;
#pragma unroll
        for (int l = 0; l < 4; l++) {
            int c = tid + l * 256;
            int row = c >> 3, kc = c & 7;
            uint32_t so = s0 + (uint32_t)(row * SA_STR + kc * 16);
            size_t ga = (size_t)(bm + row) * DIMC + k0 + kc * 8;
            cpasync16(so, Ahi + ga);
            cpasync16(so + ATILE2, Alo + ga);
        }
#pragma unroll
        for (int l = 0; l < 2; l++) {
            int c = tid + l * 256;
            int row = c >> 3, kc = c & 7;
            uint32_t so = s0 + 2 * ATILE2 + (uint32_t)(row * SA_STR + kc * 16);
            cpasync16(so, BT + (size_t)(bn + row) * DIMC + k0 + kc * 8);
        }
        CP_COMMIT();
    };

    float acc[2][4][4];
#pragma unroll
    for (int i = 0; i < 2; i++)
#pragma unroll
        for (int j = 0; j < 4; j++)
#pragma unroll
            for (int q = 0; q < 4; q++) acc[i][j][q] = 0.f;

    load_chunk(0, 0);

    const int NC = DIMC / 64;   // 8
    for (int kc = 0; kc < NC; kc++) {
        const int bf = kc & 1;
        CP_WAIT0();
        __syncthreads();
        if (kc + 1 < NC) load_chunk((kc + 1) * 64, (kc + 1) & 1);

        const uint32_t sA = sb + bf * GBUF2;
        const uint32_t sB = sA + 2 * ATILE2;
#pragma unroll
        for (int kk = 0; kk < 4; kk++) {
            uint32_t ah[2][4], al[2][4];
#pragma unroll
            for (int i = 0; i < 2; i++) {
                uint32_t a = sA + (uint32_t)((wm * 32 + i * 16 + (mm & 1) * 8 + rr) * SA_STR +
                                             kk * 32 + (mm >> 1) * 16);
                ldsm4(a, ah[i]);
                ldsm4(a + ATILE2, al[i]);
            }
#pragma unroll
            for (int jb = 0; jb < 2; jb++) {
                uint32_t bh[4];
                uint32_t a = sB + (uint32_t)((wn * 32 + jb * 16 + (mm >> 1) * 8 + rr) * SA_STR +
                                             kk * 32 + (mm & 1) * 16);
                ldsm4(a, bh);
#pragma unroll
                for (int i = 0; i < 2; i++) {
                    mma_fp16(acc[i][2 * jb],     ah[i], bh[0], bh[1]);
                    mma_fp16(acc[i][2 * jb + 1], ah[i], bh[2], bh[3]);
                    mma_fp16(acc[i][2 * jb],     al[i], bh[0], bh[1]);
                    mma_fp16(acc[i][2 * jb + 1], al[i], bh[2], bh[3]);
                }
            }
        }
    }

    if (PROJ) {
#pragma unroll
        for (int i = 0; i < 2; i++) {
            int r = bm + wm * 32 + i * 16 + gid;
#pragma unroll
            for (int j = 0; j < 4; j++) {
                int c = bn + wn * 32 + j * 8 + 2 * tg;
                float b0 = bias[c], b1 = bias[c + 1];
                *(float2*)&outF[(size_t)r * DIMC + c] =
                    make_float2(acc[i][j][0] + b0, acc[i][j][1] + b1);
                *(float2*)&outF[(size_t)(r + 8) * DIMC + c] =
                    make_float2(acc[i][j][2] + b0, acc[i][j][3] + b1);
            }
        }
    } else {
        const int seg = bn >> 9;
        const float scale = (seg == 0) ? CEXP : 1.0f;   // fold softmax scale into Q
        const size_t so = (size_t)seg * SEGSZ;
        const int cb = (bn & 511) + wn * 32;
#pragma unroll
        for (int i = 0; i < 2; i++) {
            int r = bm + wm * 32 + i * 16 + gid;
#pragma unroll
            for (int j = 0; j < 4; j++) {
                int c = cb + j * 8 + 2 * tg;
                *(uint32_t*)&oh[so + (size_t)r * DIMC + c] =
                    cvthf2(acc[i][j][0] * scale, acc[i][j][1] * scale);
                *(uint32_t*)&oh[so + (size_t)(r + 8) * DIMC + c] =
                    cvthf2(acc[i][j][2] * scale, acc[i][j][3] * scale);
            }
        }
    }
}

// ---------------------------------------------------------------------------
// mma.sync flash attention. 64-query CTAs, 128 threads, 3 CTAs/SM.
// K AND V both token-major [tok][d] in SMEM (identical 144B-stride tiles);
// V B-frags via ldmatrix.trans. S = Q(pre-scaled) x K, PV = P x V, fp16.
// ---------------------------------------------------------------------------
#define KSTRB  144
#define KBYTES (128 * KSTRB)           // 18432
#define BUFSZ  (2 * KBYTES)            // 36864 (K tile + V tile)
#define FL_SMEM (2 * BUFSZ)            // 73728

__global__ __launch_bounds__(128, 3)
void flash_mma(const __half* __restrict__ qhi,
               const __half* __restrict__ khi,
               const __half* __restrict__ vhi,
               __half* __restrict__ ath, __half* __restrict__ atl) {
    extern __shared__ char smem[];
    const uint32_t sb = smem_u32(smem);
    const int tid = threadIdx.x;
    const int w = tid >> 5, lid = tid & 31;
    const int gid = lid >> 2, tg = lid & 3;
    const int mm = lid >> 3, rr = lid & 7;
    const int m0 = blockIdx.x * 64, h = blockIdx.y, b = blockIdx.z;

    auto load_tile = [&](int n0, int bf) {
        uint32_t sk = sb + bf * BUFSZ;
        size_t kb = ((size_t)(b * SEQ + n0)) * DIMC + h * 64;
#pragma unroll
        for (int l = 0; l < 8; l++) {
            int c = tid + l * 128;               // 1024 chunks each
            int row = c >> 3, c8 = c & 7;
            uint32_t so = sk + (uint32_t)(row * KSTRB + c8 * 16);
            const size_t go = kb + (size_t)row * DIMC + c8 * 8;
            cpasync16(so, khi + go);
            cpasync16(so + KBYTES, vhi + go);
        }
        CP_COMMIT();
    };

    load_tile(0, 0);

    uint32_t qh[16];
    {
        const size_t qb = ((size_t)(b * SEQ + m0 + w * 16 + gid)) * DIMC + h * 64;
#pragma unroll
        for (int ks = 0; ks < 4; ks++) {
            qh[ks * 4 + 0] = *(const uint32_t*)(qhi + qb + ks * 16 + 2 * tg);
            qh[ks * 4 + 1] = *(const uint32_t*)(qhi + qb + 8 * DIMC + ks * 16 + 2 * tg);
            qh[ks * 4 + 2] = *(const uint32_t*)(qhi + qb + ks * 16 + 8 + 2 * tg);
            qh[ks * 4 + 3] = *(const uint32_t*)(qhi + qb + 8 * DIMC + ks * 16 + 8 + 2 * tg);
        }
    }

    float oacc[32];
#pragma unroll
    for (int i = 0; i < 32; i++) oacc[i] = 0.f;
    float lsum_lo = 0.f, lsum_hi = 0.f;

    const int NT = SEQ / 128;
    for (int it = 0; it < NT; it++) {
        const int bf = it & 1;
        CP_WAIT0();
        __syncthreads();
        if (it + 1 < NT) load_tile((it + 1) * 128, (it + 1) & 1);

        const uint32_t sbK = sb + bf * BUFSZ;
        const uint32_t sbV = sbK + KBYTES;

        float s[64];
#pragma unroll
        for (int i = 0; i < 64; i++) s[i] = 0.f;
        uint32_t pr[32];

        auto softmax_block = [&](int ks) {
            float p0 = ex2f(s[ks * 8 + 0]);
            float p1 = ex2f(s[ks * 8 + 1]);
            float p2 = ex2f(s[ks * 8 + 2]);
            float p3 = ex2f(s[ks * 8 + 3]);
            float p4 = ex2f(s[ks * 8 + 4]);
            float p5 = ex2f(s[ks * 8 + 5]);
            float p6 = ex2f(s[ks * 8 + 6]);
            float p7 = ex2f(s[ks * 8 + 7]);
            lsum_lo += (p0 + p1) + (p4 + p5);
            lsum_hi += (p2 + p3) + (p6 + p7);
            pr[ks * 4 + 0] = cvthf2(p0, p1);
            pr[ks * 4 + 1] = cvthf2(p2, p3);
            pr[ks * 4 + 2] = cvthf2(p4, p5);
            pr[ks * 4 + 3] = cvthf2(p6, p7);
        };

        // S = Qs @ K^T (K in [key][d], non-trans ldsm); softmax interleaved
#pragma unroll
        for (int nb2 = 0; nb2 < 8; nb2++) {
#pragma unroll
            for (int ks = 0; ks < 4; ks++) {
                uint32_t a = sbK + (uint32_t)((nb2 * 16 + (mm >> 1) * 8 + rr) * KSTRB +
                                              ks * 32 + (mm & 1) * 16);
                uint32_t kh[4];
                ldsm4(a, kh);
                mma_fp16(&s[nb2 * 8 + 0], &qh[ks * 4], kh[0], kh[1]);
                mma_fp16(&s[nb2 * 8 + 4], &qh[ks * 4], kh[2], kh[3]);
            }
            if (nb2 > 0) softmax_block(nb2 - 1);
        }
        softmax_block(7);

        // O += P @ V (V in [tok][d], trans ldsm gives B-frags)
#pragma unroll
        for (int nb2 = 0; nb2 < 4; nb2++) {     // d blocks of 16
#pragma unroll
            for (int ks = 0; ks < 8; ks++) {    // tok blocks of 16
                uint32_t a = sbV + (uint32_t)((ks * 16 + (mm & 1) * 8 + rr) * KSTRB +
                                              nb2 * 32 + (mm >> 1) * 16);
                uint32_t vh[4];
                ldsm4t(a, vh);
                mma_fp16(&oacc[nb2 * 8 + 0], &pr[ks * 4], vh[0], vh[1]);
                mma_fp16(&oacc[nb2 * 8 + 4], &pr[ks * 4], vh[2], vh[3]);
            }
        }
    }

    lsum_lo += __shfl_xor_sync(0xffffffffu, lsum_lo, 1);
    lsum_lo += __shfl_xor_sync(0xffffffffu, lsum_lo, 2);
    lsum_hi += __shfl_xor_sync(0xffffffffu, lsum_hi, 1);
    lsum_hi += __shfl_xor_sync(0xffffffffu, lsum_hi, 2);
    float ilo = 1.0f / lsum_lo;
    float ihi = 1.0f / lsum_hi;

    const int row_lo = m0 + w * 16 + gid;
    const size_t ob = ((size_t)(b * SEQ + row_lo)) * DIMC + h * 64 + 2 * tg;
#pragma unroll
    for (int nb = 0; nb < 8; nb++) {
        float o0 = oacc[nb * 4 + 0] * ilo, o1 = oacc[nb * 4 + 1] * ilo;
        float h0 = hfr(o0), h1 = hfr(o1);
        *(uint32_t*)&ath[ob + nb * 8] = cvthf2(h0, h1);
        *(uint32_t*)&atl[ob + nb * 8] = cvthf2(o0 - h0, o1 - h1);
        float o2 = oacc[nb * 4 + 2] * ihi, o3 = oacc[nb * 4 + 3] * ihi;
        float h2 = hfr(o2), h3 = hfr(o3);
        *(uint32_t*)&ath[ob + 8 * DIMC + nb * 8] = cvthf2(h2, h3);
        *(uint32_t*)&atl[ob + 8 * DIMC + nb * 8] = cvthf2(o2 - h2, o3 - h3);
    }
}

// ---------------------------------------------------------------------------
extern "C" void kernel_launch(void* const* d_in, const int* in_sizes, int n_in,
                              void* d_out, int out_size) {
    const float* x      = (const float*)d_in[0];
    const float* w_qkv  = (const float*)d_in[1];
    const float* w_proj = (const float*)d_in[2];
    const float* b_proj = (const float*)d_in[3];
    float* out = (float*)d_out;

    void *xh, *xl, *wq, *wp, *oh, *ath, *atl;
    cudaGetSymbolAddress(&xh, g_xh);   cudaGetSymbolAddress(&xl, g_xl);
    cudaGetSymbolAddress(&wq, g_wq);   cudaGetSymbolAddress(&wp, g_wp);
    cudaGetSymbolAddress(&oh, g_oh);
    cudaGetSymbolAddress(&ath, g_ath); cudaGetSymbolAddress(&atl, g_atl);

    typedef __half hf;

    cudaFuncSetAttribute(flash_mma,
                         cudaFuncAttributeMaxDynamicSharedMemorySize, FL_SMEM);
    cudaFuncSetAttribute(gemm_tc<false>,
                         cudaFuncAttributeMaxDynamicSharedMemorySize, GEMM_SMEM);
    cudaFuncSetAttribute(gemm_tc<true>,
                         cudaFuncAttributeMaxDynamicSharedMemorySize, GEMM_SMEM);

    // 1) splits (x -> fp16 hi/lo; weights -> fp16 hi, transposed)
    split_x<<<MROWS * DIMC / 4 / 256, 256>>>(x, (hf*)xh, (hf*)xl);
    split_wT<<<dim3(QKVC / 32, DIMC / 32), 256>>>(w_qkv, QKVC, (hf*)wq);
    split_wT<<<dim3(DIMC / 32, DIMC / 32), 256>>>(w_proj, DIMC, (hf*)wp);

    // 2) QKV projection (fp16 2-term, BK=64) -> q|k|v fp16 (Q pre-scaled)
    gemm_tc<false><<<dim3(QKVC / 64, MROWS / 128), 256, GEMM_SMEM>>>(
        (const hf*)xh, (const hf*)xl, (const hf*)wq,
        nullptr, (hf*)oh, nullptr, nullptr);

    // 3) flash attention (64-query CTAs, 3 CTAs/SM, V via ldsm.trans)
    flash_mma<<<dim3(SEQ / 64, NHEADS, BATCH), 128, FL_SMEM>>>(
        (const hf*)oh, (const hf*)oh + (size_t)SEGSZ,
        (const hf*)oh + 2 * (size_t)SEGSZ, (hf*)ath, (hf*)atl);

    // 4) output projection (fp16 2-term, BK=64) + bias -> fp32 out
    gemm_tc<true><<<dim3(DIMC / 64, MROWS / 128), 256, GEMM_SMEM>>>(
        (const hf*)ath, (const hf*)atl, (const hf*)wp,
        b_proj, nullptr, nullptr, out);
}